// round 2
// baseline (speedup 1.0000x reference)
#include <cuda_runtime.h>
#include <math.h>

#define LMAX 8192
#define HH 4

__device__ float g_nx[LMAX * 512];
__device__ float g_uvqk[LMAX * 1024];
__device__ float g_attn[LMAX * 256];
__device__ float g_y[LMAX * 256];

__device__ __forceinline__ float silu_(float z) {
    return z / (1.0f + __expf(-z));
}

// ---------------- input layernorm: (L,512) -> g_nx ----------------
__global__ void k_ln_in(const float* __restrict__ x, const float* __restrict__ w,
                        const float* __restrict__ b, int L) {
    int row = blockIdx.x;
    int t = threadIdx.x;
    const float* xr = x + (size_t)row * 512;
    float v0 = xr[t], v1 = xr[t + 256];
    float s = v0 + v1, ss = v0 * v0 + v1 * v1;
#pragma unroll
    for (int o = 16; o; o >>= 1) {
        s += __shfl_xor_sync(0xffffffffu, s, o);
        ss += __shfl_xor_sync(0xffffffffu, ss, o);
    }
    __shared__ float shs[8], shss[8];
    if ((t & 31) == 0) { shs[t >> 5] = s; shss[t >> 5] = ss; }
    __syncthreads();
    s = 0.f; ss = 0.f;
#pragma unroll
    for (int i = 0; i < 8; i++) { s += shs[i]; ss += shss[i]; }
    float mean = s * (1.0f / 512.0f);
    float var = ss * (1.0f / 512.0f) - mean * mean;
    float r = rsqrtf(var + 1e-6f);
    float* o = g_nx + (size_t)row * 512;
    o[t] = (v0 - mean) * r * w[t] + b[t];
    o[t + 256] = (v1 - mean) * r * w[t + 256] + b[t + 256];
}

// ---------------- output layernorm: g_attn (L,256) -> g_y ----------------
__global__ void k_ln_out(const float* __restrict__ w, const float* __restrict__ b, int L) {
    int row = blockIdx.x;
    int t = threadIdx.x;
    float v = g_attn[(size_t)row * 256 + t];
    float s = v, ss = v * v;
#pragma unroll
    for (int o = 16; o; o >>= 1) {
        s += __shfl_xor_sync(0xffffffffu, s, o);
        ss += __shfl_xor_sync(0xffffffffu, ss, o);
    }
    __shared__ float shs[8], shss[8];
    if ((t & 31) == 0) { shs[t >> 5] = s; shss[t >> 5] = ss; }
    __syncthreads();
    s = 0.f; ss = 0.f;
#pragma unroll
    for (int i = 0; i < 8; i++) { s += shs[i]; ss += shss[i]; }
    float mean = s * (1.0f / 256.0f);
    float var = ss * (1.0f / 256.0f) - mean * mean;
    float r = rsqrtf(var + 1e-6f);
    g_y[(size_t)row * 256 + t] = (v - mean) * r * w[t] + b[t];
}

// ---------------- GEMM1: g_uvqk = silu(g_nx @ W(512x1024) + bias) ----------------
__global__ __launch_bounds__(256) void k_gemm1(const float* __restrict__ W,
                                               const float* __restrict__ bias, int L) {
    __shared__ float As[8][132];
    __shared__ float Bs[8][128];
    int tid = threadIdx.x;
    int row0 = blockIdx.y * 128, col0 = blockIdx.x * 128;
    int arow = tid >> 1, acol = (tid & 1) * 4;
    int brow = tid >> 5, bcol = (tid & 31) * 4;
    int ty = tid >> 4, tx = tid & 15;
    float acc[8][8];
#pragma unroll
    for (int i = 0; i < 8; i++)
#pragma unroll
        for (int j = 0; j < 8; j++) acc[i][j] = 0.f;

    int lrow = min(row0 + arow, L - 1);
    const float* Aptr = g_nx + (size_t)lrow * 512 + acol;

    for (int k0 = 0; k0 < 512; k0 += 8) {
        float4 av = *(const float4*)(Aptr + k0);
        As[acol + 0][arow] = av.x;
        As[acol + 1][arow] = av.y;
        As[acol + 2][arow] = av.z;
        As[acol + 3][arow] = av.w;
        *(float4*)&Bs[brow][bcol] =
            *(const float4*)(W + (size_t)(k0 + brow) * 1024 + col0 + bcol);
        __syncthreads();
#pragma unroll
        for (int k = 0; k < 8; k++) {
            float a[8], bb[8];
            *(float4*)&a[0] = *(const float4*)&As[k][ty * 8];
            *(float4*)&a[4] = *(const float4*)&As[k][ty * 8 + 4];
            *(float4*)&bb[0] = *(const float4*)&Bs[k][tx * 8];
            *(float4*)&bb[4] = *(const float4*)&Bs[k][tx * 8 + 4];
#pragma unroll
            for (int i = 0; i < 8; i++)
#pragma unroll
                for (int j = 0; j < 8; j++) acc[i][j] += a[i] * bb[j];
        }
        __syncthreads();
    }
#pragma unroll
    for (int i = 0; i < 8; i++) {
        int r = row0 + ty * 8 + i;
        if (r >= L) break;
        float* cp = g_uvqk + (size_t)r * 1024 + col0 + tx * 8;
        float4 o0, o1;
        float z;
        z = acc[i][0] + bias[col0 + tx * 8 + 0]; o0.x = silu_(z);
        z = acc[i][1] + bias[col0 + tx * 8 + 1]; o0.y = silu_(z);
        z = acc[i][2] + bias[col0 + tx * 8 + 2]; o0.z = silu_(z);
        z = acc[i][3] + bias[col0 + tx * 8 + 3]; o0.w = silu_(z);
        z = acc[i][4] + bias[col0 + tx * 8 + 4]; o1.x = silu_(z);
        z = acc[i][5] + bias[col0 + tx * 8 + 5]; o1.y = silu_(z);
        z = acc[i][6] + bias[col0 + tx * 8 + 6]; o1.z = silu_(z);
        z = acc[i][7] + bias[col0 + tx * 8 + 7]; o1.w = silu_(z);
        *(float4*)cp = o0;
        *(float4*)(cp + 4) = o1;
    }
}

// ---------------- attention ----------------
// uvqk layout per row (1024): u[0:256) v[256:512) q[512:768) k[768:1024)
// block: 64 query rows of one (b, h); loop key tiles m0 <= q0
__global__ __launch_bounds__(256) void k_attn(const int* __restrict__ lengths,
                                              const int* __restrict__ offsets,
                                              const int* __restrict__ ntargets,
                                              const int* __restrict__ msl, int TPB) {
    int h = blockIdx.y;
    int b = blockIdx.x / TPB;
    int t = blockIdx.x % TPB;
    int len = lengths[b];
    int q0 = t * 64;
    if (q0 >= len) return;
    int off = offsets[b];
    int lim = len - ntargets[b];
    float invN = 1.0f / (float)msl[0];

    __shared__ float Qs[64][64];
    __shared__ float Ss[64][64];
    __shared__ float KVs[64][64];  // K stored transposed, then reused for V plain

    int tid = threadIdx.x;
    int lr = tid >> 2;           // 0..63
    int lc0 = (tid & 3) * 16;    // 16-wide column slab
    int ty = tid >> 4, tx = tid & 15;

    // load Q tile
    {
        int n = q0 + lr;
        const float* qp =
            g_uvqk + (size_t)(off + min(n, len - 1)) * 1024 + 512 + h * 64 + lc0;
#pragma unroll
        for (int i = 0; i < 4; i++) {
            float4 v = make_float4(0.f, 0.f, 0.f, 0.f);
            if (n < len) v = *(const float4*)(qp + i * 4);
            *(float4*)&Qs[lr][lc0 + i * 4] = v;
        }
    }

    float acc[4][4];
#pragma unroll
    for (int i = 0; i < 4; i++)
#pragma unroll
        for (int j = 0; j < 4; j++) acc[i][j] = 0.f;

    for (int m0 = 0; m0 <= q0; m0 += 64) {
        __syncthreads();
        // load K transposed: KVs[a][m]
        {
            int m = m0 + lr;
            const float* kp =
                g_uvqk + (size_t)(off + min(m, len - 1)) * 1024 + 768 + h * 64 + lc0;
#pragma unroll
            for (int i = 0; i < 4; i++) {
                float4 v = make_float4(0.f, 0.f, 0.f, 0.f);
                if (m < len) v = *(const float4*)(kp + i * 4);
                KVs[lc0 + i * 4 + 0][lr] = v.x;
                KVs[lc0 + i * 4 + 1][lr] = v.y;
                KVs[lc0 + i * 4 + 2][lr] = v.z;
                KVs[lc0 + i * 4 + 3][lr] = v.w;
            }
        }
        __syncthreads();
        // scores
        float s[4][4];
#pragma unroll
        for (int i = 0; i < 4; i++)
#pragma unroll
            for (int j = 0; j < 4; j++) s[i][j] = 0.f;
#pragma unroll
        for (int a = 0; a < 64; a++) {
            float qv[4], kv[4];
#pragma unroll
            for (int i = 0; i < 4; i++) qv[i] = Qs[ty * 4 + i][a];
#pragma unroll
            for (int j = 0; j < 4; j++) kv[j] = KVs[a][tx * 4 + j];
#pragma unroll
            for (int i = 0; i < 4; i++)
#pragma unroll
                for (int j = 0; j < 4; j++) s[i][j] += qv[i] * kv[j];
        }
        // silu + mask -> Ss
#pragma unroll
        for (int i = 0; i < 4; i++) {
            int n = q0 + ty * 4 + i;
            int idn = min(n, lim);
            float4 sv;
            float* svp = (float*)&sv;
#pragma unroll
            for (int j = 0; j < 4; j++) {
                int m = m0 + tx * 4 + j;
                float z = s[i][j] * 0.125f;  // alpha = A^-0.5 = 1/8
                float wv = silu_(z) * invN;
                int idm = min(m, lim);
                bool ok = (m < len) && (n < len) && ((idn > idm) || (n == m));
                svp[j] = ok ? wv : 0.f;
            }
            *(float4*)&Ss[ty * 4 + i][tx * 4] = sv;
        }
        __syncthreads();
        // load V plain: KVs[m][c]
        {
            int m = m0 + lr;
            const float* vp =
                g_uvqk + (size_t)(off + min(m, len - 1)) * 1024 + 256 + h * 64 + lc0;
#pragma unroll
            for (int i = 0; i < 4; i++) {
                float4 v = make_float4(0.f, 0.f, 0.f, 0.f);
                if (m < len) v = *(const float4*)(vp + i * 4);
                *(float4*)&KVs[lr][lc0 + i * 4] = v;
            }
        }
        __syncthreads();
        // PV
#pragma unroll
        for (int m = 0; m < 64; m++) {
            float sv[4], vv[4];
#pragma unroll
            for (int i = 0; i < 4; i++) sv[i] = Ss[ty * 4 + i][m];
#pragma unroll
            for (int j = 0; j < 4; j++) vv[j] = KVs[m][tx * 4 + j];
#pragma unroll
            for (int i = 0; i < 4; i++)
#pragma unroll
                for (int j = 0; j < 4; j++) acc[i][j] += sv[i] * vv[j];
        }
    }
    // write out
#pragma unroll
    for (int i = 0; i < 4; i++) {
        int n = q0 + ty * 4 + i;
        if (n < len) {
            *(float4*)&g_attn[(size_t)(off + n) * 256 + h * 64 + tx * 4] =
                make_float4(acc[i][0], acc[i][1], acc[i][2], acc[i][3]);
        }
    }
}

// ---------------- GEMM2: out = x + [u | x | y] @ Wout(1024x512) ----------------
__global__ __launch_bounds__(256) void k_gemm2(const float* __restrict__ x,
                                               const float* __restrict__ Wout, int L,
                                               float* __restrict__ out) {
    __shared__ float As[8][132];
    __shared__ float Bs[8][128];
    int tid = threadIdx.x;
    int row0 = blockIdx.y * 128, col0 = blockIdx.x * 128;
    int arow = tid >> 1, acol = (tid & 1) * 4;
    int brow = tid >> 5, bcol = (tid & 31) * 4;
    int ty = tid >> 4, tx = tid & 15;
    float acc[8][8];
#pragma unroll
    for (int i = 0; i < 8; i++)
#pragma unroll
        for (int j = 0; j < 8; j++) acc[i][j] = 0.f;

    int lrow = min(row0 + arow, L - 1);

    for (int k0 = 0; k0 < 1024; k0 += 8) {
        int j = k0 + acol;  // global k index of this thread's float4 (segment-aligned)
        const float* p;
        if (j < 256)
            p = g_uvqk + (size_t)lrow * 1024 + j;          // u
        else if (j < 768)
            p = x + (size_t)lrow * 512 + (j - 256);        // x
        else
            p = g_y + (size_t)lrow * 256 + (j - 768);      // y
        float4 av = *(const float4*)p;
        As[acol + 0][arow] = av.x;
        As[acol + 1][arow] = av.y;
        As[acol + 2][arow] = av.z;
        As[acol + 3][arow] = av.w;
        *(float4*)&Bs[brow][bcol] =
            *(const float4*)(Wout + (size_t)(k0 + brow) * 512 + col0 + bcol);
        __syncthreads();
#pragma unroll
        for (int k = 0; k < 8; k++) {
            float a[8], bb[8];
            *(float4*)&a[0] = *(const float4*)&As[k][ty * 8];
            *(float4*)&a[4] = *(const float4*)&As[k][ty * 8 + 4];
            *(float4*)&bb[0] = *(const float4*)&Bs[k][tx * 8];
            *(float4*)&bb[4] = *(const float4*)&Bs[k][tx * 8 + 4];
#pragma unroll
            for (int i = 0; i < 8; i++)
#pragma unroll
                for (int jj = 0; jj < 8; jj++) acc[i][jj] += a[i] * bb[jj];
        }
        __syncthreads();
    }
#pragma unroll
    for (int i = 0; i < 8; i++) {
        int r = row0 + ty * 8 + i;
        if (r >= L) break;
        const float* xp = x + (size_t)r * 512 + col0 + tx * 8;
        float* cp = out + (size_t)r * 512 + col0 + tx * 8;
        float4 x0 = *(const float4*)xp;
        float4 x1 = *(const float4*)(xp + 4);
        float4 o0, o1;
        o0.x = x0.x + acc[i][0];
        o0.y = x0.y + acc[i][1];
        o0.z = x0.z + acc[i][2];
        o0.w = x0.w + acc[i][3];
        o1.x = x1.x + acc[i][4];
        o1.y = x1.y + acc[i][5];
        o1.z = x1.z + acc[i][6];
        o1.w = x1.w + acc[i][7];
        *(float4*)cp = o0;
        *(float4*)(cp + 4) = o1;
    }
}

extern "C" void kernel_launch(void* const* d_in, const int* in_sizes, int n_in,
                              void* d_out, int out_size) {
    const float* x = (const float*)d_in[0];
    const int* xl = (const int*)d_in[1];
    const int* xo = (const int*)d_in[2];
    const int* msl = (const int*)d_in[3];
    const int* nt = (const int*)d_in[4];
    const float* Wu = (const float*)d_in[5];
    const float* bu = (const float*)d_in[6];
    const float* inw = (const float*)d_in[7];
    const float* inb = (const float*)d_in[8];
    const float* onw = (const float*)d_in[9];
    const float* onb = (const float*)d_in[10];
    const float* Wo = (const float*)d_in[11];
    float* out = (float*)d_out;

    int L = in_sizes[0] / 512;
    int B = in_sizes[1];

    k_ln_in<<<L, 256>>>(x, inw, inb, L);

    dim3 g1(1024 / 128, (L + 127) / 128);
    k_gemm1<<<g1, 256>>>(Wu, bu, L);

    int TPB = (L + 63) / 64;  // upper bound on 64-row query tiles per batch
    dim3 ga(B * TPB, HH);
    k_attn<<<ga, 256>>>(xl, xo, nt, msl, TPB);

    k_ln_out<<<L, 256>>>(onw, onb, L);

    dim3 g2(512 / 128, (L + 127) / 128);
    k_gemm2<<<g2, 256>>>(x, Wo, L, out);
}

// round 5
// speedup vs baseline: 1.4506x; 1.4506x over previous
#include <cuda_runtime.h>
#include <math.h>

#define LMAX 8192
#define HH 4

__device__ float g_nx[LMAX * 512];
__device__ float g_uvqk[LMAX * 1024];
__device__ float g_attn[LMAX * 256];
__device__ float g_y[LMAX * 256];

__device__ __forceinline__ float silu_(float z) {
    return z / (1.0f + __expf(-z));
}

__device__ __forceinline__ unsigned tf32_(float f) {
    unsigned r;
    asm("cvt.rna.tf32.f32 %0, %1;" : "=r"(r) : "f"(f));
    return r;
}

__device__ __forceinline__ void mma8(float* d, unsigned a0, unsigned a1, unsigned a2,
                                     unsigned a3, unsigned b0, unsigned b1) {
    asm volatile(
        "mma.sync.aligned.m16n8k8.row.col.f32.tf32.tf32.f32 "
        "{%0,%1,%2,%3}, {%4,%5,%6,%7}, {%8,%9}, {%0,%1,%2,%3};\n"
        : "+f"(d[0]), "+f"(d[1]), "+f"(d[2]), "+f"(d[3])
        : "r"(a0), "r"(a1), "r"(a2), "r"(a3), "r"(b0), "r"(b1));
}

// ---------------- input layernorm: (L,512) -> g_nx ----------------
__global__ void k_ln_in(const float* __restrict__ x, const float* __restrict__ w,
                        const float* __restrict__ b, int L) {
    int row = blockIdx.x;
    int t = threadIdx.x;
    const float* xr = x + (size_t)row * 512;
    float v0 = xr[t], v1 = xr[t + 256];
    float s = v0 + v1, ss = v0 * v0 + v1 * v1;
#pragma unroll
    for (int o = 16; o; o >>= 1) {
        s += __shfl_xor_sync(0xffffffffu, s, o);
        ss += __shfl_xor_sync(0xffffffffu, ss, o);
    }
    __shared__ float shs[8], shss[8];
    if ((t & 31) == 0) { shs[t >> 5] = s; shss[t >> 5] = ss; }
    __syncthreads();
    s = 0.f; ss = 0.f;
#pragma unroll
    for (int i = 0; i < 8; i++) { s += shs[i]; ss += shss[i]; }
    float mean = s * (1.0f / 512.0f);
    float var = ss * (1.0f / 512.0f) - mean * mean;
    float r = rsqrtf(var + 1e-6f);
    float* o = g_nx + (size_t)row * 512;
    o[t] = (v0 - mean) * r * w[t] + b[t];
    o[t + 256] = (v1 - mean) * r * w[t + 256] + b[t + 256];
}

// ---------------- output layernorm: g_attn (L,256) -> g_y ----------------
__global__ void k_ln_out(const float* __restrict__ w, const float* __restrict__ b, int L) {
    int row = blockIdx.x;
    int t = threadIdx.x;
    float v = g_attn[(size_t)row * 256 + t];
    float s = v, ss = v * v;
#pragma unroll
    for (int o = 16; o; o >>= 1) {
        s += __shfl_xor_sync(0xffffffffu, s, o);
        ss += __shfl_xor_sync(0xffffffffu, ss, o);
    }
    __shared__ float shs[8], shss[8];
    if ((t & 31) == 0) { shs[t >> 5] = s; shss[t >> 5] = ss; }
    __syncthreads();
    s = 0.f; ss = 0.f;
#pragma unroll
    for (int i = 0; i < 8; i++) { s += shs[i]; ss += shss[i]; }
    float mean = s * (1.0f / 256.0f);
    float var = ss * (1.0f / 256.0f) - mean * mean;
    float r = rsqrtf(var + 1e-6f);
    g_y[(size_t)row * 256 + t] = (v - mean) * r * w[t] + b[t];
}

// ---------------- GEMM1 (tensor core tf32): g_uvqk = silu(g_nx @ W + bias) ----------------
// M=L, K=512, N=1024. Block 128x128, 8 warps (2x4), warp 64x32 via m16n8k8.
__global__ __launch_bounds__(256) void k_gemm1_tc(const float* __restrict__ W,
                                                  const float* __restrict__ bias, int L) {
    __shared__ unsigned As[128][36];
    __shared__ unsigned Bs[32][136];
    int tid = threadIdx.x, lane = tid & 31, wid = tid >> 5;
    int wm = wid >> 2, wn = wid & 3;
    int l4 = lane >> 2, l3 = lane & 3;
    int row0 = blockIdx.y * 128, col0 = blockIdx.x * 128;

    float acc[4][4][4];
#pragma unroll
    for (int i = 0; i < 4; i++)
#pragma unroll
        for (int j = 0; j < 4; j++)
#pragma unroll
            for (int q = 0; q < 4; q++) acc[i][j][q] = 0.f;

    float4 aR[4], bR[4];
    int ar_r = tid >> 3, ar_c = (tid & 7) * 4;
    int br_r = tid >> 5, br_c = (tid & 31) * 4;

    auto loadg = [&](int k0) {
#pragma unroll
        for (int p = 0; p < 4; p++) {
            int gr = min(row0 + ar_r + p * 32, L - 1);
            aR[p] = *(const float4*)(g_nx + (size_t)gr * 512 + k0 + ar_c);
            bR[p] = *(const float4*)(W + (size_t)(k0 + br_r + p * 8) * 1024 + col0 + br_c);
        }
    };
    auto stores = [&]() {
#pragma unroll
        for (int p = 0; p < 4; p++) {
            uint4 ta;
            ta.x = tf32_(aR[p].x); ta.y = tf32_(aR[p].y);
            ta.z = tf32_(aR[p].z); ta.w = tf32_(aR[p].w);
            *(uint4*)&As[ar_r + p * 32][ar_c] = ta;
            uint4 tb;
            tb.x = tf32_(bR[p].x); tb.y = tf32_(bR[p].y);
            tb.z = tf32_(bR[p].z); tb.w = tf32_(bR[p].w);
            *(uint4*)&Bs[br_r + p * 8][br_c] = tb;
        }
    };
    auto compute = [&]() {
#pragma unroll
        for (int kk = 0; kk < 32; kk += 8) {
            unsigned b0[4], b1[4];
#pragma unroll
            for (int nt = 0; nt < 4; nt++) {
                int bc = wn * 32 + nt * 8 + l4;
                b0[nt] = Bs[kk + l3][bc];
                b1[nt] = Bs[kk + l3 + 4][bc];
            }
#pragma unroll
            for (int mt = 0; mt < 4; mt++) {
                int ar = wm * 64 + mt * 16 + l4;
                unsigned a0 = As[ar][kk + l3];
                unsigned a1 = As[ar + 8][kk + l3];
                unsigned a2 = As[ar][kk + l3 + 4];
                unsigned a3 = As[ar + 8][kk + l3 + 4];
#pragma unroll
                for (int nt = 0; nt < 4; nt++)
                    mma8(acc[mt][nt], a0, a1, a2, a3, b0[nt], b1[nt]);
            }
        }
    };

    loadg(0);
    stores();
    __syncthreads();
    for (int k0 = 32; k0 < 512; k0 += 32) {
        loadg(k0);
        compute();
        __syncthreads();
        stores();
        __syncthreads();
    }
    compute();

#pragma unroll
    for (int mt = 0; mt < 4; mt++)
#pragma unroll
        for (int nt = 0; nt < 4; nt++) {
            int r = row0 + wm * 64 + mt * 16 + l4;
            int c = col0 + wn * 32 + nt * 8 + l3 * 2;
            float2 bb = *(const float2*)(bias + c);
            if (r < L) {
                float2 o;
                o.x = silu_(acc[mt][nt][0] + bb.x);
                o.y = silu_(acc[mt][nt][1] + bb.y);
                *(float2*)(g_uvqk + (size_t)r * 1024 + c) = o;
            }
            if (r + 8 < L) {
                float2 o;
                o.x = silu_(acc[mt][nt][2] + bb.x);
                o.y = silu_(acc[mt][nt][3] + bb.y);
                *(float2*)(g_uvqk + (size_t)(r + 8) * 1024 + c) = o;
            }
        }
}

// ---------------- GEMM2 (tensor core tf32): out = x + [u|x|y] @ Wout ----------------
// M=L, K=1024, N=512.
__global__ __launch_bounds__(256) void k_gemm2_tc(const float* __restrict__ x,
                                                  const float* __restrict__ Wout, int L,
                                                  float* __restrict__ out) {
    __shared__ unsigned As[128][36];
    __shared__ unsigned Bs[32][136];
    int tid = threadIdx.x, lane = tid & 31, wid = tid >> 5;
    int wm = wid >> 2, wn = wid & 3;
    int l4 = lane >> 2, l3 = lane & 3;
    int row0 = blockIdx.y * 128, col0 = blockIdx.x * 128;

    float acc[4][4][4];
#pragma unroll
    for (int i = 0; i < 4; i++)
#pragma unroll
        for (int j = 0; j < 4; j++)
#pragma unroll
            for (int q = 0; q < 4; q++) acc[i][j][q] = 0.f;

    float4 aR[4], bR[4];
    int ar_r = tid >> 3, ar_c = (tid & 7) * 4;
    int br_r = tid >> 5, br_c = (tid & 31) * 4;

    auto loadg = [&](int k0) {
        int j = k0 + ar_c;
        const float* base;
        int pitch;
        if (j < 256) { base = g_uvqk + j; pitch = 1024; }
        else if (j < 768) { base = x + (j - 256); pitch = 512; }
        else { base = g_y + (j - 768); pitch = 256; }
#pragma unroll
        for (int p = 0; p < 4; p++) {
            int gr = min(row0 + ar_r + p * 32, L - 1);
            aR[p] = *(const float4*)(base + (size_t)gr * pitch);
            bR[p] = *(const float4*)(Wout + (size_t)(k0 + br_r + p * 8) * 512 + col0 + br_c);
        }
    };
    auto stores = [&]() {
#pragma unroll
        for (int p = 0; p < 4; p++) {
            uint4 ta;
            ta.x = tf32_(aR[p].x); ta.y = tf32_(aR[p].y);
            ta.z = tf32_(aR[p].z); ta.w = tf32_(aR[p].w);
            *(uint4*)&As[ar_r + p * 32][ar_c] = ta;
            uint4 tb;
            tb.x = tf32_(bR[p].x); tb.y = tf32_(bR[p].y);
            tb.z = tf32_(bR[p].z); tb.w = tf32_(bR[p].w);
            *(uint4*)&Bs[br_r + p * 8][br_c] = tb;
        }
    };
    auto compute = [&]() {
#pragma unroll
        for (int kk = 0; kk < 32; kk += 8) {
            unsigned b0[4], b1[4];
#pragma unroll
            for (int nt = 0; nt < 4; nt++) {
                int bc = wn * 32 + nt * 8 + l4;
                b0[nt] = Bs[kk + l3][bc];
                b1[nt] = Bs[kk + l3 + 4][bc];
            }
#pragma unroll
            for (int mt = 0; mt < 4; mt++) {
                int ar = wm * 64 + mt * 16 + l4;
                unsigned a0 = As[ar][kk + l3];
                unsigned a1 = As[ar + 8][kk + l3];
                unsigned a2 = As[ar][kk + l3 + 4];
                unsigned a3 = As[ar + 8][kk + l3 + 4];
#pragma unroll
                for (int nt = 0; nt < 4; nt++)
                    mma8(acc[mt][nt], a0, a1, a2, a3, b0[nt], b1[nt]);
            }
        }
    };

    loadg(0);
    stores();
    __syncthreads();
    for (int k0 = 32; k0 < 1024; k0 += 32) {
        loadg(k0);
        compute();
        __syncthreads();
        stores();
        __syncthreads();
    }
    compute();

#pragma unroll
    for (int mt = 0; mt < 4; mt++)
#pragma unroll
        for (int nt = 0; nt < 4; nt++) {
            int r = row0 + wm * 64 + mt * 16 + l4;
            int c = col0 + wn * 32 + nt * 8 + l3 * 2;
            if (r < L) {
                float2 xv = *(const float2*)(x + (size_t)r * 512 + c);
                float2 o;
                o.x = xv.x + acc[mt][nt][0];
                o.y = xv.y + acc[mt][nt][1];
                *(float2*)(out + (size_t)r * 512 + c) = o;
            }
            if (r + 8 < L) {
                float2 xv = *(const float2*)(x + (size_t)(r + 8) * 512 + c);
                float2 o;
                o.x = xv.x + acc[mt][nt][2];
                o.y = xv.y + acc[mt][nt][3];
                *(float2*)(out + (size_t)(r + 8) * 512 + c) = o;
            }
        }
}

// ---------------- attention ----------------
// uvqk layout per row (1024): u[0:256) v[256:512) q[512:768) k[768:1024)
// Qs stored transposed [a][n]; Ss stored [m][n] pitch 68; KVs holds K^T then V.
__global__ __launch_bounds__(256) void k_attn(const int* __restrict__ lengths,
                                              const int* __restrict__ offsets,
                                              const int* __restrict__ ntargets,
                                              const int* __restrict__ msl, int TPB) {
    extern __shared__ float sm[];
    float(*Qs)[64] = (float(*)[64])sm;                   // 64*64
    float(*Ss)[68] = (float(*)[68])(sm + 4096);          // 64*68
    float(*KVs)[64] = (float(*)[64])(sm + 4096 + 4352);  // 64*64

    int h = blockIdx.y;
    int b = blockIdx.x / TPB;
    int t = blockIdx.x % TPB;
    int len = lengths[b];
    int q0 = t * 64;
    if (q0 >= len) return;
    int off = offsets[b];
    int lim = len - ntargets[b];
    float invN = 1.0f / (float)msl[0];

    int tid = threadIdx.x;
    int lr = tid >> 2;
    int lc0 = (tid & 3) * 16;
    int ty = tid >> 4, tx = tid & 15;

    // load Q tile transposed: Qs[a][n]
    {
        int n = q0 + lr;
        const float* qp =
            g_uvqk + (size_t)(off + min(n, len - 1)) * 1024 + 512 + h * 64 + lc0;
#pragma unroll
        for (int i = 0; i < 4; i++) {
            float4 v = make_float4(0.f, 0.f, 0.f, 0.f);
            if (n < len) v = *(const float4*)(qp + i * 4);
            Qs[lc0 + i * 4 + 0][lr] = v.x;
            Qs[lc0 + i * 4 + 1][lr] = v.y;
            Qs[lc0 + i * 4 + 2][lr] = v.z;
            Qs[lc0 + i * 4 + 3][lr] = v.w;
        }
    }

    float acc[4][4];
#pragma unroll
    for (int i = 0; i < 4; i++)
#pragma unroll
        for (int j = 0; j < 4; j++) acc[i][j] = 0.f;

    for (int m0 = 0; m0 <= q0; m0 += 64) {
        __syncthreads();
        // load K transposed: KVs[a][m]
        {
            int m = m0 + lr;
            const float* kp =
                g_uvqk + (size_t)(off + min(m, len - 1)) * 1024 + 768 + h * 64 + lc0;
#pragma unroll
            for (int i = 0; i < 4; i++) {
                float4 v = make_float4(0.f, 0.f, 0.f, 0.f);
                if (m < len) v = *(const float4*)(kp + i * 4);
                KVs[lc0 + i * 4 + 0][lr] = v.x;
                KVs[lc0 + i * 4 + 1][lr] = v.y;
                KVs[lc0 + i * 4 + 2][lr] = v.z;
                KVs[lc0 + i * 4 + 3][lr] = v.w;
            }
        }
        __syncthreads();
        // scores: s[i][j], i = q-local (ty*4+i), j = k-local (tx*4+j)
        float s[4][4];
#pragma unroll
        for (int i = 0; i < 4; i++)
#pragma unroll
            for (int j = 0; j < 4; j++) s[i][j] = 0.f;
#pragma unroll
        for (int a = 0; a < 64; a++) {
            float4 qv = *(const float4*)&Qs[a][ty * 4];
            float4 kv = *(const float4*)&KVs[a][tx * 4];
            float qa[4] = {qv.x, qv.y, qv.z, qv.w};
            float ka[4] = {kv.x, kv.y, kv.z, kv.w};
#pragma unroll
            for (int i = 0; i < 4; i++)
#pragma unroll
                for (int j = 0; j < 4; j++) s[i][j] += qa[i] * ka[j];
        }
        // silu + mask
#pragma unroll
        for (int i = 0; i < 4; i++) {
            int n = q0 + ty * 4 + i;
            int idn = min(n, lim);
#pragma unroll
            for (int j = 0; j < 4; j++) {
                int m = m0 + tx * 4 + j;
                float z = s[i][j] * 0.125f;
                float wv = silu_(z) * invN;
                int idm = min(m, lim);
                bool ok = (m < len) && (n < len) && ((idn > idm) || (n == m));
                s[i][j] = ok ? wv : 0.f;
            }
        }
        // store transposed: Ss[m][n]
#pragma unroll
        for (int j = 0; j < 4; j++) {
            *(float4*)&Ss[tx * 4 + j][ty * 4] =
                make_float4(s[0][j], s[1][j], s[2][j], s[3][j]);
        }
        __syncthreads();
        // load V plain: KVs[m][c]
        {
            int m = m0 + lr;
            const float* vp =
                g_uvqk + (size_t)(off + min(m, len - 1)) * 1024 + 256 + h * 64 + lc0;
#pragma unroll
            for (int i = 0; i < 4; i++) {
                float4 v = make_float4(0.f, 0.f, 0.f, 0.f);
                if (m < len) v = *(const float4*)(vp + i * 4);
                *(float4*)&KVs[lr][lc0 + i * 4] = v;
            }
        }
        __syncthreads();
        // PV
#pragma unroll
        for (int m = 0; m < 64; m++) {
            float4 svv = *(const float4*)&Ss[m][ty * 4];
            float4 vvv = *(const float4*)&KVs[m][tx * 4];
            float sa[4] = {svv.x, svv.y, svv.z, svv.w};
            float va[4] = {vvv.x, vvv.y, vvv.z, vvv.w};
#pragma unroll
            for (int i = 0; i < 4; i++)
#pragma unroll
                for (int j = 0; j < 4; j++) acc[i][j] += sa[i] * va[j];
        }
    }
    // write out
#pragma unroll
    for (int i = 0; i < 4; i++) {
        int n = q0 + ty * 4 + i;
        if (n < len) {
            *(float4*)&g_attn[(size_t)(off + n) * 256 + h * 64 + tx * 4] =
                make_float4(acc[i][0], acc[i][1], acc[i][2], acc[i][3]);
        }
    }
}

extern "C" void kernel_launch(void* const* d_in, const int* in_sizes, int n_in,
                              void* d_out, int out_size) {
    const float* x = (const float*)d_in[0];
    const int* xl = (const int*)d_in[1];
    const int* xo = (const int*)d_in[2];
    const int* msl = (const int*)d_in[3];
    const int* nt = (const int*)d_in[4];
    const float* Wu = (const float*)d_in[5];
    const float* bu = (const float*)d_in[6];
    const float* inw = (const float*)d_in[7];
    const float* inb = (const float*)d_in[8];
    const float* onw = (const float*)d_in[9];
    const float* onb = (const float*)d_in[10];
    const float* Wo = (const float*)d_in[11];
    float* out = (float*)d_out;

    int L = in_sizes[0] / 512;
    int B = in_sizes[1];

    static bool attr_set = false;
    if (!attr_set) {
        cudaFuncSetAttribute(k_attn, cudaFuncAttributeMaxDynamicSharedMemorySize, 50176);
        attr_set = true;
    }

    k_ln_in<<<L, 256>>>(x, inw, inb, L);

    dim3 g1(1024 / 128, (L + 127) / 128);
    k_gemm1_tc<<<g1, 256>>>(Wu, bu, L);

    int TPB = (L + 63) / 64;
    dim3 ga(B * TPB, HH);
    k_attn<<<ga, 256, 50176>>>(xl, xo, nt, msl, TPB);

    k_ln_out<<<L, 256>>>(onw, onb, L);

    dim3 g2(512 / 128, (L + 127) / 128);
    k_gemm2_tc<<<g2, 256>>>(x, Wo, L, out);
}

// round 8
// speedup vs baseline: 2.5338x; 1.7467x over previous
#include <cuda_runtime.h>
#include <math.h>

#define LMAX 8192
#define HH 4

__device__ float g_nx[LMAX * 512];
__device__ float g_uvqk[LMAX * 1024];
__device__ float g_attn[LMAX * 256];
__device__ float g_y[LMAX * 256];

__device__ __forceinline__ float silu_(float z) {
    return z / (1.0f + __expf(-z));
}

__device__ __forceinline__ unsigned tf32_(float f) {
    unsigned r;
    asm("cvt.rna.tf32.f32 %0, %1;" : "=r"(r) : "f"(f));
    return r;
}

__device__ __forceinline__ void mma8(float* d, unsigned a0, unsigned a1, unsigned a2,
                                     unsigned a3, unsigned b0, unsigned b1) {
    asm volatile(
        "mma.sync.aligned.m16n8k8.row.col.f32.tf32.tf32.f32 "
        "{%0,%1,%2,%3}, {%4,%5,%6,%7}, {%8,%9}, {%0,%1,%2,%3};\n"
        : "+f"(d[0]), "+f"(d[1]), "+f"(d[2]), "+f"(d[3])
        : "r"(a0), "r"(a1), "r"(a2), "r"(a3), "r"(b0), "r"(b1));
}

// ---------------- input layernorm: (L,512) -> g_nx ----------------
__global__ void k_ln_in(const float* __restrict__ x, const float* __restrict__ w,
                        const float* __restrict__ b, int L) {
    int row = blockIdx.x;
    int t = threadIdx.x;
    const float* xr = x + (size_t)row * 512;
    float v0 = xr[t], v1 = xr[t + 256];
    float s = v0 + v1, ss = v0 * v0 + v1 * v1;
#pragma unroll
    for (int o = 16; o; o >>= 1) {
        s += __shfl_xor_sync(0xffffffffu, s, o);
        ss += __shfl_xor_sync(0xffffffffu, ss, o);
    }
    __shared__ float shs[8], shss[8];
    if ((t & 31) == 0) { shs[t >> 5] = s; shss[t >> 5] = ss; }
    __syncthreads();
    s = 0.f; ss = 0.f;
#pragma unroll
    for (int i = 0; i < 8; i++) { s += shs[i]; ss += shss[i]; }
    float mean = s * (1.0f / 512.0f);
    float var = ss * (1.0f / 512.0f) - mean * mean;
    float r = rsqrtf(var + 1e-6f);
    float* o = g_nx + (size_t)row * 512;
    o[t] = (v0 - mean) * r * w[t] + b[t];
    o[t + 256] = (v1 - mean) * r * w[t + 256] + b[t + 256];
}

// ---------------- output layernorm: g_attn (L,256) -> g_y ----------------
__global__ void k_ln_out(const float* __restrict__ w, const float* __restrict__ b, int L) {
    int row = blockIdx.x;
    int t = threadIdx.x;
    float v = g_attn[(size_t)row * 256 + t];
    float s = v, ss = v * v;
#pragma unroll
    for (int o = 16; o; o >>= 1) {
        s += __shfl_xor_sync(0xffffffffu, s, o);
        ss += __shfl_xor_sync(0xffffffffu, ss, o);
    }
    __shared__ float shs[8], shss[8];
    if ((t & 31) == 0) { shs[t >> 5] = s; shss[t >> 5] = ss; }
    __syncthreads();
    s = 0.f; ss = 0.f;
#pragma unroll
    for (int i = 0; i < 8; i++) { s += shs[i]; ss += shss[i]; }
    float mean = s * (1.0f / 256.0f);
    float var = ss * (1.0f / 256.0f) - mean * mean;
    float r = rsqrtf(var + 1e-6f);
    g_y[(size_t)row * 256 + t] = (v - mean) * r * w[t] + b[t];
}

// ---------------- GEMM1 (tensor core tf32): g_uvqk = silu(g_nx @ W + bias) ----------------
__global__ __launch_bounds__(256) void k_gemm1_tc(const float* __restrict__ W,
                                                  const float* __restrict__ bias, int L) {
    __shared__ unsigned As[128][36];
    __shared__ unsigned Bs[32][136];
    int tid = threadIdx.x, lane = tid & 31, wid = tid >> 5;
    int wm = wid >> 2, wn = wid & 3;
    int l4 = lane >> 2, l3 = lane & 3;
    int row0 = blockIdx.y * 128, col0 = blockIdx.x * 128;

    float acc[4][4][4];
#pragma unroll
    for (int i = 0; i < 4; i++)
#pragma unroll
        for (int j = 0; j < 4; j++)
#pragma unroll
            for (int q = 0; q < 4; q++) acc[i][j][q] = 0.f;

    float4 aR[4], bR[4];
    int ar_r = tid >> 3, ar_c = (tid & 7) * 4;
    int br_r = tid >> 5, br_c = (tid & 31) * 4;

    auto loadg = [&](int k0) {
#pragma unroll
        for (int p = 0; p < 4; p++) {
            int gr = min(row0 + ar_r + p * 32, L - 1);
            aR[p] = *(const float4*)(g_nx + (size_t)gr * 512 + k0 + ar_c);
            bR[p] = *(const float4*)(W + (size_t)(k0 + br_r + p * 8) * 1024 + col0 + br_c);
        }
    };
    auto stores = [&]() {
#pragma unroll
        for (int p = 0; p < 4; p++) {
            uint4 ta;
            ta.x = tf32_(aR[p].x); ta.y = tf32_(aR[p].y);
            ta.z = tf32_(aR[p].z); ta.w = tf32_(aR[p].w);
            *(uint4*)&As[ar_r + p * 32][ar_c] = ta;
            uint4 tb;
            tb.x = tf32_(bR[p].x); tb.y = tf32_(bR[p].y);
            tb.z = tf32_(bR[p].z); tb.w = tf32_(bR[p].w);
            *(uint4*)&Bs[br_r + p * 8][br_c] = tb;
        }
    };
    auto compute = [&]() {
#pragma unroll
        for (int kk = 0; kk < 32; kk += 8) {
            unsigned b0[4], b1[4];
#pragma unroll
            for (int nt = 0; nt < 4; nt++) {
                int bc = wn * 32 + nt * 8 + l4;
                b0[nt] = Bs[kk + l3][bc];
                b1[nt] = Bs[kk + l3 + 4][bc];
            }
#pragma unroll
            for (int mt = 0; mt < 4; mt++) {
                int ar = wm * 64 + mt * 16 + l4;
                unsigned a0 = As[ar][kk + l3];
                unsigned a1 = As[ar + 8][kk + l3];
                unsigned a2 = As[ar][kk + l3 + 4];
                unsigned a3 = As[ar + 8][kk + l3 + 4];
#pragma unroll
                for (int nt = 0; nt < 4; nt++)
                    mma8(acc[mt][nt], a0, a1, a2, a3, b0[nt], b1[nt]);
            }
        }
    };

    loadg(0);
    stores();
    __syncthreads();
    for (int k0 = 32; k0 < 512; k0 += 32) {
        loadg(k0);
        compute();
        __syncthreads();
        stores();
        __syncthreads();
    }
    compute();

#pragma unroll
    for (int mt = 0; mt < 4; mt++)
#pragma unroll
        for (int nt = 0; nt < 4; nt++) {
            int r = row0 + wm * 64 + mt * 16 + l4;
            int c = col0 + wn * 32 + nt * 8 + l3 * 2;
            float2 bb = *(const float2*)(bias + c);
            if (r < L) {
                float2 o;
                o.x = silu_(acc[mt][nt][0] + bb.x);
                o.y = silu_(acc[mt][nt][1] + bb.y);
                *(float2*)(g_uvqk + (size_t)r * 1024 + c) = o;
            }
            if (r + 8 < L) {
                float2 o;
                o.x = silu_(acc[mt][nt][2] + bb.x);
                o.y = silu_(acc[mt][nt][3] + bb.y);
                *(float2*)(g_uvqk + (size_t)(r + 8) * 1024 + c) = o;
            }
        }
}

// ---------------- GEMM2 (tensor core tf32): out = x + [u|x|y] @ Wout ----------------
__global__ __launch_bounds__(256) void k_gemm2_tc(const float* __restrict__ x,
                                                  const float* __restrict__ Wout, int L,
                                                  float* __restrict__ out) {
    __shared__ unsigned As[128][36];
    __shared__ unsigned Bs[32][136];
    int tid = threadIdx.x, lane = tid & 31, wid = tid >> 5;
    int wm = wid >> 2, wn = wid & 3;
    int l4 = lane >> 2, l3 = lane & 3;
    int row0 = blockIdx.y * 128, col0 = blockIdx.x * 128;

    float acc[4][4][4];
#pragma unroll
    for (int i = 0; i < 4; i++)
#pragma unroll
        for (int j = 0; j < 4; j++)
#pragma unroll
            for (int q = 0; q < 4; q++) acc[i][j][q] = 0.f;

    float4 aR[4], bR[4];
    int ar_r = tid >> 3, ar_c = (tid & 7) * 4;
    int br_r = tid >> 5, br_c = (tid & 31) * 4;

    auto loadg = [&](int k0) {
        int j = k0 + ar_c;
        const float* base;
        int pitch;
        if (j < 256) { base = g_uvqk + j; pitch = 1024; }
        else if (j < 768) { base = x + (j - 256); pitch = 512; }
        else { base = g_y + (j - 768); pitch = 256; }
#pragma unroll
        for (int p = 0; p < 4; p++) {
            int gr = min(row0 + ar_r + p * 32, L - 1);
            aR[p] = *(const float4*)(base + (size_t)gr * pitch);
            bR[p] = *(const float4*)(Wout + (size_t)(k0 + br_r + p * 8) * 512 + col0 + br_c);
        }
    };
    auto stores = [&]() {
#pragma unroll
        for (int p = 0; p < 4; p++) {
            uint4 ta;
            ta.x = tf32_(aR[p].x); ta.y = tf32_(aR[p].y);
            ta.z = tf32_(aR[p].z); ta.w = tf32_(aR[p].w);
            *(uint4*)&As[ar_r + p * 32][ar_c] = ta;
            uint4 tb;
            tb.x = tf32_(bR[p].x); tb.y = tf32_(bR[p].y);
            tb.z = tf32_(bR[p].z); tb.w = tf32_(bR[p].w);
            *(uint4*)&Bs[br_r + p * 8][br_c] = tb;
        }
    };
    auto compute = [&]() {
#pragma unroll
        for (int kk = 0; kk < 32; kk += 8) {
            unsigned b0[4], b1[4];
#pragma unroll
            for (int nt = 0; nt < 4; nt++) {
                int bc = wn * 32 + nt * 8 + l4;
                b0[nt] = Bs[kk + l3][bc];
                b1[nt] = Bs[kk + l3 + 4][bc];
            }
#pragma unroll
            for (int mt = 0; mt < 4; mt++) {
                int ar = wm * 64 + mt * 16 + l4;
                unsigned a0 = As[ar][kk + l3];
                unsigned a1 = As[ar + 8][kk + l3];
                unsigned a2 = As[ar][kk + l3 + 4];
                unsigned a3 = As[ar + 8][kk + l3 + 4];
#pragma unroll
                for (int nt = 0; nt < 4; nt++)
                    mma8(acc[mt][nt], a0, a1, a2, a3, b0[nt], b1[nt]);
            }
        }
    };

    loadg(0);
    stores();
    __syncthreads();
    for (int k0 = 32; k0 < 1024; k0 += 32) {
        loadg(k0);
        compute();
        __syncthreads();
        stores();
        __syncthreads();
    }
    compute();

#pragma unroll
    for (int mt = 0; mt < 4; mt++)
#pragma unroll
        for (int nt = 0; nt < 4; nt++) {
            int r = row0 + wm * 64 + mt * 16 + l4;
            int c = col0 + wn * 32 + nt * 8 + l3 * 2;
            if (r < L) {
                float2 xv = *(const float2*)(x + (size_t)r * 512 + c);
                float2 o;
                o.x = xv.x + acc[mt][nt][0];
                o.y = xv.y + acc[mt][nt][1];
                *(float2*)(out + (size_t)r * 512 + c) = o;
            }
            if (r + 8 < L) {
                float2 xv = *(const float2*)(x + (size_t)(r + 8) * 512 + c);
                float2 o;
                o.x = xv.x + acc[mt][nt][2];
                o.y = xv.y + acc[mt][nt][3];
                *(float2*)(out + (size_t)(r + 8) * 512 + c) = o;
            }
        }
}

// ---------------- attention (tensor core tf32) ----------------
// uvqk layout per row (1024): u[0:256) v[256:512) q[512:768) k[768:1024)
// Block = (b, h, 64-query tile). 8 warps: wm in [0,4) x wn in [0,2).
// Warp computes 16x32 of the 64x64 score tile and 16x32 of the output tile.
__global__ __launch_bounds__(256) void k_attn_tc(const int* __restrict__ lengths,
                                                 const int* __restrict__ offsets,
                                                 const int* __restrict__ ntargets,
                                                 const int* __restrict__ msl, int TPB) {
    extern __shared__ unsigned smu[];
    unsigned(*Qs)[68] = (unsigned(*)[68])smu;             // 64x68 tf32
    unsigned(*Ks)[68] = (unsigned(*)[68])(smu + 4352);    // 64x68 tf32
    float(*Ss)[68] = (float(*)[68])(smu + 8704);          // 64x68 f32
    unsigned(*Vs)[72] = (unsigned(*)[72])(smu + 13056);   // 64x72 tf32

    int h = blockIdx.y;
    int b = blockIdx.x / TPB;
    int t = blockIdx.x % TPB;
    int len = lengths[b];
    int q0 = t * 64;
    if (q0 >= len) return;
    int off = offsets[b];
    int lim = len - ntargets[b];
    float invN = 1.0f / (float)msl[0];

    int tid = threadIdx.x, lane = tid & 31, wid = tid >> 5;
    int wm = wid >> 1, wn = wid & 1;
    int l4 = lane >> 2, l3 = lane & 3;
    int lr = tid >> 2, lc0 = (tid & 3) * 16;

    // ---- load Q tile (rows q0..q0+63) into Qs as tf32 ----
    {
        int n = q0 + lr;
        const float* qp =
            g_uvqk + (size_t)(off + min(n, len - 1)) * 1024 + 512 + h * 64 + lc0;
#pragma unroll
        for (int i = 0; i < 4; i++) {
            float4 v = make_float4(0.f, 0.f, 0.f, 0.f);
            if (n < len) v = *(const float4*)(qp + i * 4);
            uint4 tv;
            tv.x = tf32_(v.x); tv.y = tf32_(v.y); tv.z = tf32_(v.z); tv.w = tf32_(v.w);
            *(uint4*)&Qs[lr][lc0 + i * 4] = tv;
        }
    }
    __syncthreads();

    // ---- Q fragments to registers (rows wm*16..+16, all 64 a) ----
    unsigned qf[8][4];
#pragma unroll
    for (int ks = 0; ks < 8; ks++) {
        qf[ks][0] = Qs[wm * 16 + l4][ks * 8 + l3];
        qf[ks][1] = Qs[wm * 16 + l4 + 8][ks * 8 + l3];
        qf[ks][2] = Qs[wm * 16 + l4][ks * 8 + l3 + 4];
        qf[ks][3] = Qs[wm * 16 + l4 + 8][ks * 8 + l3 + 4];
    }

    float oacc[4][4];
#pragma unroll
    for (int i = 0; i < 4; i++)
#pragma unroll
        for (int j = 0; j < 4; j++) oacc[i][j] = 0.f;

    for (int m0 = 0; m0 <= q0; m0 += 64) {
        __syncthreads();  // previous PV reads done before overwriting Ks/Vs
        // ---- load K, V tiles (rows m0..m0+63) ----
        {
            int m = m0 + lr;
            const float* kp =
                g_uvqk + (size_t)(off + min(m, len - 1)) * 1024 + 768 + h * 64 + lc0;
            const float* vp =
                g_uvqk + (size_t)(off + min(m, len - 1)) * 1024 + 256 + h * 64 + lc0;
            bool ok = m < len;
#pragma unroll
            for (int i = 0; i < 4; i++) {
                float4 v = make_float4(0.f, 0.f, 0.f, 0.f);
                if (ok) v = *(const float4*)(kp + i * 4);
                uint4 tv;
                tv.x = tf32_(v.x); tv.y = tf32_(v.y); tv.z = tf32_(v.z); tv.w = tf32_(v.w);
                *(uint4*)&Ks[lr][lc0 + i * 4] = tv;
                float4 w = make_float4(0.f, 0.f, 0.f, 0.f);
                if (ok) w = *(const float4*)(vp + i * 4);
                uint4 tw;
                tw.x = tf32_(w.x); tw.y = tf32_(w.y); tw.z = tf32_(w.z); tw.w = tf32_(w.w);
                *(uint4*)&Vs[lr][lc0 + i * 4] = tw;
            }
        }
        __syncthreads();

        // ---- QK^T: warp computes S[wm*16..+16][wn*32..+32] ----
        float sacc[4][4];
#pragma unroll
        for (int i = 0; i < 4; i++)
#pragma unroll
            for (int j = 0; j < 4; j++) sacc[i][j] = 0.f;
#pragma unroll
        for (int ks = 0; ks < 8; ks++) {
            unsigned b0[4], b1[4];
#pragma unroll
            for (int nt = 0; nt < 4; nt++) {
                int mr = wn * 32 + nt * 8 + l4;
                b0[nt] = Ks[mr][ks * 8 + l3];
                b1[nt] = Ks[mr][ks * 8 + l3 + 4];
            }
#pragma unroll
            for (int nt = 0; nt < 4; nt++)
                mma8(sacc[nt], qf[ks][0], qf[ks][1], qf[ks][2], qf[ks][3], b0[nt], b1[nt]);
        }

        // ---- silu + mask, store S^(n,m) to Ss ----
        {
            int n_lo = q0 + wm * 16 + l4;
            int n_hi = n_lo + 8;
            int idn_lo = min(n_lo, lim), idn_hi = min(n_hi, lim);
            bool nok_lo = n_lo < len, nok_hi = n_hi < len;
#pragma unroll
            for (int nt = 0; nt < 4; nt++) {
                int m_ = m0 + wn * 32 + nt * 8 + 2 * l3;
#pragma unroll
                for (int jj = 0; jj < 2; jj++) {
                    int m = m_ + jj;
                    int idm = min(m, lim);
                    bool mok = m < len;
                    float z0 = sacc[nt][jj] * 0.125f;
                    float w0 = silu_(z0) * invN;
                    bool ok0 = mok && nok_lo && ((idn_lo > idm) || (n_lo == m));
                    sacc[nt][jj] = ok0 ? w0 : 0.f;
                    float z1 = sacc[nt][jj + 2] * 0.125f;
                    float w1 = silu_(z1) * invN;
                    bool ok1 = mok && nok_hi && ((idn_hi > idm) || (n_hi == m));
                    sacc[nt][jj + 2] = ok1 ? w1 : 0.f;
                }
                int sr = wm * 16 + l4;
                int sc = wn * 32 + nt * 8 + 2 * l3;
                *(float2*)&Ss[sr][sc] = make_float2(sacc[nt][0], sacc[nt][1]);
                *(float2*)&Ss[sr + 8][sc] = make_float2(sacc[nt][2], sacc[nt][3]);
            }
        }
        __syncthreads();

        // ---- PV: O[wm*16..+16][wn*32..+32] += S @ V ----
#pragma unroll
        for (int km = 0; km < 8; km++) {
            unsigned a0 = __float_as_uint(Ss[wm * 16 + l4][km * 8 + l3]);
            unsigned a1 = __float_as_uint(Ss[wm * 16 + l4 + 8][km * 8 + l3]);
            unsigned a2 = __float_as_uint(Ss[wm * 16 + l4][km * 8 + l3 + 4]);
            unsigned a3 = __float_as_uint(Ss[wm * 16 + l4 + 8][km * 8 + l3 + 4]);
#pragma unroll
            for (int nt = 0; nt < 4; nt++) {
                unsigned b0 = Vs[km * 8 + l3][wn * 32 + nt * 8 + l4];
                unsigned b1 = Vs[km * 8 + l3 + 4][wn * 32 + nt * 8 + l4];
                mma8(oacc[nt], a0, a1, a2, a3, b0, b1);
            }
        }
    }

    // ---- write output ----
#pragma unroll
    for (int nt = 0; nt < 4; nt++) {
        int col = h * 64 + wn * 32 + nt * 8 + 2 * l3;
        int n = q0 + wm * 16 + l4;
        if (n < len)
            *(float2*)&g_attn[(size_t)(off + n) * 256 + col] =
                make_float2(oacc[nt][0], oacc[nt][1]);
        if (n + 8 < len)
            *(float2*)&g_attn[(size_t)(off + n + 8) * 256 + col] =
                make_float2(oacc[nt][2], oacc[nt][3]);
    }
}

extern "C" void kernel_launch(void* const* d_in, const int* in_sizes, int n_in,
                              void* d_out, int out_size) {
    const float* x = (const float*)d_in[0];
    const int* xl = (const int*)d_in[1];
    const int* xo = (const int*)d_in[2];
    const int* msl = (const int*)d_in[3];
    const int* nt = (const int*)d_in[4];
    const float* Wu = (const float*)d_in[5];
    const float* bu = (const float*)d_in[6];
    const float* inw = (const float*)d_in[7];
    const float* inb = (const float*)d_in[8];
    const float* onw = (const float*)d_in[9];
    const float* onb = (const float*)d_in[10];
    const float* Wo = (const float*)d_in[11];
    float* out = (float*)d_out;

    int L = in_sizes[0] / 512;
    int B = in_sizes[1];

    static bool attr_set = false;
    if (!attr_set) {
        cudaFuncSetAttribute(k_attn_tc, cudaFuncAttributeMaxDynamicSharedMemorySize,
                             70656);
        attr_set = true;
    }

    k_ln_in<<<L, 256>>>(x, inw, inb, L);

    dim3 g1(1024 / 128, (L + 127) / 128);
    k_gemm1_tc<<<g1, 256>>>(Wu, bu, L);

    int TPB = (L + 63) / 64;
    dim3 ga(B * TPB, HH);
    k_attn_tc<<<ga, 256, 70656>>>(xl, xo, nt, msl, TPB);

    k_ln_out<<<L, 256>>>(onw, onb, L);

    dim3 g2(512 / 128, (L + 127) / 128);
    k_gemm2_tc<<<g2, 256>>>(x, Wo, L, out);
}

// round 9
// speedup vs baseline: 2.8473x; 1.1237x over previous
#include <cuda_runtime.h>
#include <math.h>

#define LMAX 8192
#define HH 4

__device__ float g_nx[LMAX * 512];    // tf32-rounded
__device__ float g_uvqk[LMAX * 1024]; // tf32-rounded
__device__ float g_attn[LMAX * 256];  // fp32
__device__ float g_y[LMAX * 256];     // tf32-rounded

__device__ __forceinline__ float silu_(float z) {
    return z / (1.0f + __expf(-z));
}

__device__ __forceinline__ unsigned tf32_(float f) {
    unsigned r;
    asm("cvt.rna.tf32.f32 %0, %1;" : "=r"(r) : "f"(f));
    return r;
}

__device__ __forceinline__ float tf32f_(float f) {
    return __uint_as_float(tf32_(f));
}

__device__ __forceinline__ void mma8(float* d, unsigned a0, unsigned a1, unsigned a2,
                                     unsigned a3, unsigned b0, unsigned b1) {
    asm volatile(
        "mma.sync.aligned.m16n8k8.row.col.f32.tf32.tf32.f32 "
        "{%0,%1,%2,%3}, {%4,%5,%6,%7}, {%8,%9}, {%0,%1,%2,%3};\n"
        : "+f"(d[0]), "+f"(d[1]), "+f"(d[2]), "+f"(d[3])
        : "r"(a0), "r"(a1), "r"(a2), "r"(a3), "r"(b0), "r"(b1));
}

__device__ __forceinline__ void cpa16(void* s, const void* g) {
    unsigned sa = (unsigned)__cvta_generic_to_shared(s);
    asm volatile("cp.async.cg.shared.global [%0], [%1], 16;" ::"r"(sa), "l"(g));
}
#define CP_COMMIT asm volatile("cp.async.commit_group;")
#define CP_WAIT0 asm volatile("cp.async.wait_group 0;")

// ---------------- input layernorm: (L,512) -> g_nx (tf32-rounded) ----------------
__global__ void k_ln_in(const float* __restrict__ x, const float* __restrict__ w,
                        const float* __restrict__ b, int L) {
    int row = blockIdx.x;
    int t = threadIdx.x;
    const float* xr = x + (size_t)row * 512;
    float v0 = xr[t], v1 = xr[t + 256];
    float s = v0 + v1, ss = v0 * v0 + v1 * v1;
#pragma unroll
    for (int o = 16; o; o >>= 1) {
        s += __shfl_xor_sync(0xffffffffu, s, o);
        ss += __shfl_xor_sync(0xffffffffu, ss, o);
    }
    __shared__ float shs[8], shss[8];
    if ((t & 31) == 0) { shs[t >> 5] = s; shss[t >> 5] = ss; }
    __syncthreads();
    s = 0.f; ss = 0.f;
#pragma unroll
    for (int i = 0; i < 8; i++) { s += shs[i]; ss += shss[i]; }
    float mean = s * (1.0f / 512.0f);
    float var = ss * (1.0f / 512.0f) - mean * mean;
    float r = rsqrtf(var + 1e-6f);
    float* o = g_nx + (size_t)row * 512;
    o[t] = tf32f_((v0 - mean) * r * w[t] + b[t]);
    o[t + 256] = tf32f_((v1 - mean) * r * w[t + 256] + b[t + 256]);
}

// ---------------- output layernorm: g_attn (L,256) -> g_y (tf32-rounded) ----------------
__global__ void k_ln_out(const float* __restrict__ w, const float* __restrict__ b, int L) {
    int row = blockIdx.x;
    int t = threadIdx.x;
    float v = g_attn[(size_t)row * 256 + t];
    float s = v, ss = v * v;
#pragma unroll
    for (int o = 16; o; o >>= 1) {
        s += __shfl_xor_sync(0xffffffffu, s, o);
        ss += __shfl_xor_sync(0xffffffffu, ss, o);
    }
    __shared__ float shs[8], shss[8];
    if ((t & 31) == 0) { shs[t >> 5] = s; shss[t >> 5] = ss; }
    __syncthreads();
    s = 0.f; ss = 0.f;
#pragma unroll
    for (int i = 0; i < 8; i++) { s += shs[i]; ss += shss[i]; }
    float mean = s * (1.0f / 256.0f);
    float var = ss * (1.0f / 256.0f) - mean * mean;
    float r = rsqrtf(var + 1e-6f);
    g_y[(size_t)row * 256 + t] = tf32f_((v - mean) * r * w[t] + b[t]);
}

// ---------------- GEMM core (shared by gemm1/gemm2 via lambdas) ----------------
// Block 128x128, 8 warps (2x4), warp 64x32 via m16n8k8. 2-stage cp.async pipeline.
// smem: As [2][128][36] unsigned, Bs [2][32][136] unsigned (raw tf32-rounded bits).
#define AS_PITCH 36
#define BS_PITCH 136
#define AS_WORDS (128 * AS_PITCH)
#define BS_WORDS (32 * BS_PITCH)
#define GEMM_SMEM ((2 * (AS_WORDS + BS_WORDS)) * 4)

// ---------------- GEMM1: g_uvqk = silu(g_nx @ W(512x1024) + bias), tf32-rounded ----------------
__global__ __launch_bounds__(256) void k_gemm1_tc(const float* __restrict__ W,
                                                  const float* __restrict__ bias, int L) {
    extern __shared__ unsigned smu[];
    unsigned* AsB = smu;                  // [2][AS_WORDS]
    unsigned* BsB = smu + 2 * AS_WORDS;   // [2][BS_WORDS]
    int tid = threadIdx.x, lane = tid & 31, wid = tid >> 5;
    int wm = wid >> 2, wn = wid & 3;
    int l4 = lane >> 2, l3 = lane & 3;
    int row0 = blockIdx.y * 128, col0 = blockIdx.x * 128;

    float acc[4][4][4];
#pragma unroll
    for (int i = 0; i < 4; i++)
#pragma unroll
        for (int j = 0; j < 4; j++)
#pragma unroll
            for (int q = 0; q < 4; q++) acc[i][j][q] = 0.f;

    int ar_r = tid >> 3, ar_c = (tid & 7) * 4;
    int br_r = tid >> 5, br_c = (tid & 31) * 4;

    auto prefetch = [&](int k0, int st) {
        unsigned* As = AsB + st * AS_WORDS;
        unsigned* Bs = BsB + st * BS_WORDS;
#pragma unroll
        for (int p = 0; p < 4; p++) {
            int gr = min(row0 + ar_r + p * 32, L - 1);
            cpa16(&As[(ar_r + p * 32) * AS_PITCH + ar_c],
                  g_nx + (size_t)gr * 512 + k0 + ar_c);
            cpa16(&Bs[(br_r + p * 8) * BS_PITCH + br_c],
                  W + (size_t)(k0 + br_r + p * 8) * 1024 + col0 + br_c);
        }
        CP_COMMIT;
    };
    auto compute = [&](int st) {
        unsigned* As = AsB + st * AS_WORDS;
        unsigned* Bs = BsB + st * BS_WORDS;
#pragma unroll
        for (int kk = 0; kk < 32; kk += 8) {
            unsigned b0[4], b1[4];
#pragma unroll
            for (int nt = 0; nt < 4; nt++) {
                int bc = wn * 32 + nt * 8 + l4;
                b0[nt] = Bs[(kk + l3) * BS_PITCH + bc];
                b1[nt] = Bs[(kk + l3 + 4) * BS_PITCH + bc];
            }
#pragma unroll
            for (int mt = 0; mt < 4; mt++) {
                int ar = wm * 64 + mt * 16 + l4;
                unsigned a0 = As[ar * AS_PITCH + kk + l3];
                unsigned a1 = As[(ar + 8) * AS_PITCH + kk + l3];
                unsigned a2 = As[ar * AS_PITCH + kk + l3 + 4];
                unsigned a3 = As[(ar + 8) * AS_PITCH + kk + l3 + 4];
#pragma unroll
                for (int nt = 0; nt < 4; nt++)
                    mma8(acc[mt][nt], a0, a1, a2, a3, b0[nt], b1[nt]);
            }
        }
    };

    prefetch(0, 0);
    CP_WAIT0;
    __syncthreads();
    int cur = 0;
    for (int k0 = 0; k0 < 512; k0 += 32) {
        if (k0 + 32 < 512) prefetch(k0 + 32, cur ^ 1);
        compute(cur);
        if (k0 + 32 < 512) {
            CP_WAIT0;
            __syncthreads();
            cur ^= 1;
        }
    }

#pragma unroll
    for (int mt = 0; mt < 4; mt++)
#pragma unroll
        for (int nt = 0; nt < 4; nt++) {
            int r = row0 + wm * 64 + mt * 16 + l4;
            int c = col0 + wn * 32 + nt * 8 + l3 * 2;
            float2 bb = *(const float2*)(bias + c);
            if (r < L) {
                float2 o;
                o.x = tf32f_(silu_(acc[mt][nt][0] + bb.x));
                o.y = tf32f_(silu_(acc[mt][nt][1] + bb.y));
                *(float2*)(g_uvqk + (size_t)r * 1024 + c) = o;
            }
            if (r + 8 < L) {
                float2 o;
                o.x = tf32f_(silu_(acc[mt][nt][2] + bb.x));
                o.y = tf32f_(silu_(acc[mt][nt][3] + bb.y));
                *(float2*)(g_uvqk + (size_t)(r + 8) * 1024 + c) = o;
            }
        }
}

// ---------------- GEMM2: out = x + [u|x|y] @ Wout(1024x512) ----------------
__global__ __launch_bounds__(256) void k_gemm2_tc(const float* __restrict__ x,
                                                  const float* __restrict__ Wout, int L,
                                                  float* __restrict__ out) {
    extern __shared__ unsigned smu[];
    unsigned* AsB = smu;
    unsigned* BsB = smu + 2 * AS_WORDS;
    int tid = threadIdx.x, lane = tid & 31, wid = tid >> 5;
    int wm = wid >> 2, wn = wid & 3;
    int l4 = lane >> 2, l3 = lane & 3;
    int row0 = blockIdx.y * 128, col0 = blockIdx.x * 128;

    float acc[4][4][4];
#pragma unroll
    for (int i = 0; i < 4; i++)
#pragma unroll
        for (int j = 0; j < 4; j++)
#pragma unroll
            for (int q = 0; q < 4; q++) acc[i][j][q] = 0.f;

    int ar_r = tid >> 3, ar_c = (tid & 7) * 4;
    int br_r = tid >> 5, br_c = (tid & 31) * 4;

    auto prefetch = [&](int k0, int st) {
        unsigned* As = AsB + st * AS_WORDS;
        unsigned* Bs = BsB + st * BS_WORDS;
        int j = k0 + ar_c;
        const float* base;
        int pitch;
        if (j < 256) { base = g_uvqk + j; pitch = 1024; }
        else if (j < 768) { base = x + (j - 256); pitch = 512; }
        else { base = g_y + (j - 768); pitch = 256; }
#pragma unroll
        for (int p = 0; p < 4; p++) {
            int gr = min(row0 + ar_r + p * 32, L - 1);
            cpa16(&As[(ar_r + p * 32) * AS_PITCH + ar_c], base + (size_t)gr * pitch);
            cpa16(&Bs[(br_r + p * 8) * BS_PITCH + br_c],
                  Wout + (size_t)(k0 + br_r + p * 8) * 512 + col0 + br_c);
        }
        CP_COMMIT;
    };
    auto compute = [&](int st) {
        unsigned* As = AsB + st * AS_WORDS;
        unsigned* Bs = BsB + st * BS_WORDS;
#pragma unroll
        for (int kk = 0; kk < 32; kk += 8) {
            unsigned b0[4], b1[4];
#pragma unroll
            for (int nt = 0; nt < 4; nt++) {
                int bc = wn * 32 + nt * 8 + l4;
                b0[nt] = Bs[(kk + l3) * BS_PITCH + bc];
                b1[nt] = Bs[(kk + l3 + 4) * BS_PITCH + bc];
            }
#pragma unroll
            for (int mt = 0; mt < 4; mt++) {
                int ar = wm * 64 + mt * 16 + l4;
                unsigned a0 = As[ar * AS_PITCH + kk + l3];
                unsigned a1 = As[(ar + 8) * AS_PITCH + kk + l3];
                unsigned a2 = As[ar * AS_PITCH + kk + l3 + 4];
                unsigned a3 = As[(ar + 8) * AS_PITCH + kk + l3 + 4];
#pragma unroll
                for (int nt = 0; nt < 4; nt++)
                    mma8(acc[mt][nt], a0, a1, a2, a3, b0[nt], b1[nt]);
            }
        }
    };

    prefetch(0, 0);
    CP_WAIT0;
    __syncthreads();
    int cur = 0;
    for (int k0 = 0; k0 < 1024; k0 += 32) {
        if (k0 + 32 < 1024) prefetch(k0 + 32, cur ^ 1);
        compute(cur);
        if (k0 + 32 < 1024) {
            CP_WAIT0;
            __syncthreads();
            cur ^= 1;
        }
    }

#pragma unroll
    for (int mt = 0; mt < 4; mt++)
#pragma unroll
        for (int nt = 0; nt < 4; nt++) {
            int r = row0 + wm * 64 + mt * 16 + l4;
            int c = col0 + wn * 32 + nt * 8 + l3 * 2;
            if (r < L) {
                float2 xv = *(const float2*)(x + (size_t)r * 512 + c);
                float2 o;
                o.x = xv.x + acc[mt][nt][0];
                o.y = xv.y + acc[mt][nt][1];
                *(float2*)(out + (size_t)r * 512 + c) = o;
            }
            if (r + 8 < L) {
                float2 xv = *(const float2*)(x + (size_t)(r + 8) * 512 + c);
                float2 o;
                o.x = xv.x + acc[mt][nt][2];
                o.y = xv.y + acc[mt][nt][3];
                *(float2*)(out + (size_t)(r + 8) * 512 + c) = o;
            }
        }
}

// ---------------- attention (tensor core tf32, pre-rounded inputs) ----------------
__global__ __launch_bounds__(256) void k_attn_tc(const int* __restrict__ lengths,
                                                 const int* __restrict__ offsets,
                                                 const int* __restrict__ ntargets,
                                                 const int* __restrict__ msl, int TPB) {
    extern __shared__ unsigned smu[];
    unsigned(*Qs)[68] = (unsigned(*)[68])smu;            // 64x68 tf32
    unsigned(*Ks)[68] = (unsigned(*)[68])(smu + 4352);   // 64x68 tf32
    float(*Ss)[68] = (float(*)[68])(smu + 8704);         // 64x68 f32
    unsigned(*Vs)[72] = (unsigned(*)[72])(smu + 13056);  // 64x72 tf32

    int h = blockIdx.y;
    int b = blockIdx.x / TPB;
    int t = blockIdx.x % TPB;
    int len = lengths[b];
    int q0 = t * 64;
    if (q0 >= len) return;
    int off = offsets[b];
    int lim = len - ntargets[b];
    float invN = 1.0f / (float)msl[0];

    int tid = threadIdx.x, lane = tid & 31, wid = tid >> 5;
    int wm = wid >> 1, wn = wid & 1;
    int l4 = lane >> 2, l3 = lane & 3;
    int lr = tid >> 2, lc0 = (tid & 3) * 16;

    const uint4 zero4 = make_uint4(0u, 0u, 0u, 0u);

    // ---- load Q tile (rows q0..q0+63) into Qs (raw, already tf32-rounded) ----
    {
        int n = q0 + lr;
        const uint4* qp = (const uint4*)(g_uvqk + (size_t)(off + min(n, len - 1)) * 1024 +
                                         512 + h * 64 + lc0);
        bool ok = n < len;
#pragma unroll
        for (int i = 0; i < 4; i++)
            *(uint4*)&Qs[lr][lc0 + i * 4] = ok ? qp[i] : zero4;
    }
    __syncthreads();

    unsigned qf[8][4];
#pragma unroll
    for (int ks = 0; ks < 8; ks++) {
        qf[ks][0] = Qs[wm * 16 + l4][ks * 8 + l3];
        qf[ks][1] = Qs[wm * 16 + l4 + 8][ks * 8 + l3];
        qf[ks][2] = Qs[wm * 16 + l4][ks * 8 + l3 + 4];
        qf[ks][3] = Qs[wm * 16 + l4 + 8][ks * 8 + l3 + 4];
    }

    float oacc[4][4];
#pragma unroll
    for (int i = 0; i < 4; i++)
#pragma unroll
        for (int j = 0; j < 4; j++) oacc[i][j] = 0.f;

    for (int m0 = 0; m0 <= q0; m0 += 64) {
        __syncthreads();
        {
            int m = m0 + lr;
            const uint4* kp = (const uint4*)(g_uvqk +
                                             (size_t)(off + min(m, len - 1)) * 1024 +
                                             768 + h * 64 + lc0);
            const uint4* vp = (const uint4*)(g_uvqk +
                                             (size_t)(off + min(m, len - 1)) * 1024 +
                                             256 + h * 64 + lc0);
            bool ok = m < len;
#pragma unroll
            for (int i = 0; i < 4; i++) {
                *(uint4*)&Ks[lr][lc0 + i * 4] = ok ? kp[i] : zero4;
                *(uint4*)&Vs[lr][lc0 + i * 4] = ok ? vp[i] : zero4;
            }
        }
        __syncthreads();

        float sacc[4][4];
#pragma unroll
        for (int i = 0; i < 4; i++)
#pragma unroll
            for (int j = 0; j < 4; j++) sacc[i][j] = 0.f;
#pragma unroll
        for (int ks = 0; ks < 8; ks++) {
            unsigned b0[4], b1[4];
#pragma unroll
            for (int nt = 0; nt < 4; nt++) {
                int mr = wn * 32 + nt * 8 + l4;
                b0[nt] = Ks[mr][ks * 8 + l3];
                b1[nt] = Ks[mr][ks * 8 + l3 + 4];
            }
#pragma unroll
            for (int nt = 0; nt < 4; nt++)
                mma8(sacc[nt], qf[ks][0], qf[ks][1], qf[ks][2], qf[ks][3], b0[nt], b1[nt]);
        }

        {
            int n_lo = q0 + wm * 16 + l4;
            int n_hi = n_lo + 8;
            int idn_lo = min(n_lo, lim), idn_hi = min(n_hi, lim);
            bool nok_lo = n_lo < len, nok_hi = n_hi < len;
#pragma unroll
            for (int nt = 0; nt < 4; nt++) {
                int m_ = m0 + wn * 32 + nt * 8 + 2 * l3;
#pragma unroll
                for (int jj = 0; jj < 2; jj++) {
                    int m = m_ + jj;
                    int idm = min(m, lim);
                    bool mok = m < len;
                    float z0 = sacc[nt][jj] * 0.125f;
                    float w0 = silu_(z0) * invN;
                    bool ok0 = mok && nok_lo && ((idn_lo > idm) || (n_lo == m));
                    sacc[nt][jj] = ok0 ? w0 : 0.f;
                    float z1 = sacc[nt][jj + 2] * 0.125f;
                    float w1 = silu_(z1) * invN;
                    bool ok1 = mok && nok_hi && ((idn_hi > idm) || (n_hi == m));
                    sacc[nt][jj + 2] = ok1 ? w1 : 0.f;
                }
                int sr = wm * 16 + l4;
                int sc = wn * 32 + nt * 8 + 2 * l3;
                *(float2*)&Ss[sr][sc] = make_float2(sacc[nt][0], sacc[nt][1]);
                *(float2*)&Ss[sr + 8][sc] = make_float2(sacc[nt][2], sacc[nt][3]);
            }
        }
        __syncthreads();

#pragma unroll
        for (int km = 0; km < 8; km++) {
            unsigned a0 = __float_as_uint(Ss[wm * 16 + l4][km * 8 + l3]);
            unsigned a1 = __float_as_uint(Ss[wm * 16 + l4 + 8][km * 8 + l3]);
            unsigned a2 = __float_as_uint(Ss[wm * 16 + l4][km * 8 + l3 + 4]);
            unsigned a3 = __float_as_uint(Ss[wm * 16 + l4 + 8][km * 8 + l3 + 4]);
#pragma unroll
            for (int nt = 0; nt < 4; nt++) {
                unsigned b0 = Vs[km * 8 + l3][wn * 32 + nt * 8 + l4];
                unsigned b1 = Vs[km * 8 + l3 + 4][wn * 32 + nt * 8 + l4];
                mma8(oacc[nt], a0, a1, a2, a3, b0, b1);
            }
        }
    }

#pragma unroll
    for (int nt = 0; nt < 4; nt++) {
        int col = h * 64 + wn * 32 + nt * 8 + 2 * l3;
        int n = q0 + wm * 16 + l4;
        if (n < len)
            *(float2*)&g_attn[(size_t)(off + n) * 256 + col] =
                make_float2(oacc[nt][0], oacc[nt][1]);
        if (n + 8 < len)
            *(float2*)&g_attn[(size_t)(off + n + 8) * 256 + col] =
                make_float2(oacc[nt][2], oacc[nt][3]);
    }
}

extern "C" void kernel_launch(void* const* d_in, const int* in_sizes, int n_in,
                              void* d_out, int out_size) {
    const float* x = (const float*)d_in[0];
    const int* xl = (const int*)d_in[1];
    const int* xo = (const int*)d_in[2];
    const int* msl = (const int*)d_in[3];
    const int* nt = (const int*)d_in[4];
    const float* Wu = (const float*)d_in[5];
    const float* bu = (const float*)d_in[6];
    const float* inw = (const float*)d_in[7];
    const float* inb = (const float*)d_in[8];
    const float* onw = (const float*)d_in[9];
    const float* onb = (const float*)d_in[10];
    const float* Wo = (const float*)d_in[11];
    float* out = (float*)d_out;

    int L = in_sizes[0] / 512;
    int B = in_sizes[1];

    static bool attr_set = false;
    if (!attr_set) {
        cudaFuncSetAttribute(k_attn_tc, cudaFuncAttributeMaxDynamicSharedMemorySize,
                             70656);
        cudaFuncSetAttribute(k_gemm1_tc, cudaFuncAttributeMaxDynamicSharedMemorySize,
                             GEMM_SMEM);
        cudaFuncSetAttribute(k_gemm2_tc, cudaFuncAttributeMaxDynamicSharedMemorySize,
                             GEMM_SMEM);
        attr_set = true;
    }

    k_ln_in<<<L, 256>>>(x, inw, inb, L);

    dim3 g1(1024 / 128, (L + 127) / 128);
    k_gemm1_tc<<<g1, 256, GEMM_SMEM>>>(Wu, bu, L);

    int TPB = (L + 63) / 64;
    dim3 ga(B * TPB, HH);
    k_attn_tc<<<ga, 256, 70656>>>(xl, xo, nt, msl, TPB);

    k_ln_out<<<L, 256>>>(onw, onb, L);

    dim3 g2(512 / 128, (L + 127) / 128);
    k_gemm2_tc<<<g2, 256, GEMM_SMEM>>>(x, Wo, L, out);
}

// round 10
// speedup vs baseline: 3.0920x; 1.0860x over previous
#include <cuda_runtime.h>
#include <math.h>

#define LMAX 8192
#define HH 4

__device__ float g_nx[LMAX * 512];    // tf32-rounded
__device__ float g_uvqk[LMAX * 1024]; // tf32-rounded
__device__ float g_attn[LMAX * 256];  // fp32
__device__ float g_y[LMAX * 256];     // tf32-rounded

__device__ __forceinline__ float silu_(float z) {
    return z / (1.0f + __expf(-z));
}

__device__ __forceinline__ unsigned tf32_(float f) {
    unsigned r;
    asm("cvt.rna.tf32.f32 %0, %1;" : "=r"(r) : "f"(f));
    return r;
}

__device__ __forceinline__ float tf32f_(float f) {
    return __uint_as_float(tf32_(f));
}

__device__ __forceinline__ void mma8(float* d, unsigned a0, unsigned a1, unsigned a2,
                                     unsigned a3, unsigned b0, unsigned b1) {
    asm volatile(
        "mma.sync.aligned.m16n8k8.row.col.f32.tf32.tf32.f32 "
        "{%0,%1,%2,%3}, {%4,%5,%6,%7}, {%8,%9}, {%0,%1,%2,%3};\n"
        : "+f"(d[0]), "+f"(d[1]), "+f"(d[2]), "+f"(d[3])
        : "r"(a0), "r"(a1), "r"(a2), "r"(a3), "r"(b0), "r"(b1));
}

__device__ __forceinline__ void cpa16(void* s, const void* g) {
    unsigned sa = (unsigned)__cvta_generic_to_shared(s);
    asm volatile("cp.async.cg.shared.global [%0], [%1], 16;" ::"r"(sa), "l"(g));
}
// zero-fill variant: src-size = 0 when !ok
__device__ __forceinline__ void cpa16z(void* s, const void* g, bool ok) {
    unsigned sa = (unsigned)__cvta_generic_to_shared(s);
    int sz = ok ? 16 : 0;
    asm volatile("cp.async.cg.shared.global [%0], [%1], 16, %2;" ::"r"(sa), "l"(g),
                 "r"(sz));
}
#define CP_COMMIT asm volatile("cp.async.commit_group;")
#define CP_WAIT0 asm volatile("cp.async.wait_group 0;")

// ---------------- input layernorm: (L,512) -> g_nx (tf32-rounded) ----------------
__global__ void k_ln_in(const float* __restrict__ x, const float* __restrict__ w,
                        const float* __restrict__ b, int L) {
    int row = blockIdx.x;
    int t = threadIdx.x;
    const float* xr = x + (size_t)row * 512;
    float v0 = xr[t], v1 = xr[t + 256];
    float s = v0 + v1, ss = v0 * v0 + v1 * v1;
#pragma unroll
    for (int o = 16; o; o >>= 1) {
        s += __shfl_xor_sync(0xffffffffu, s, o);
        ss += __shfl_xor_sync(0xffffffffu, ss, o);
    }
    __shared__ float shs[8], shss[8];
    if ((t & 31) == 0) { shs[t >> 5] = s; shss[t >> 5] = ss; }
    __syncthreads();
    s = 0.f; ss = 0.f;
#pragma unroll
    for (int i = 0; i < 8; i++) { s += shs[i]; ss += shss[i]; }
    float mean = s * (1.0f / 512.0f);
    float var = ss * (1.0f / 512.0f) - mean * mean;
    float r = rsqrtf(var + 1e-6f);
    float* o = g_nx + (size_t)row * 512;
    o[t] = tf32f_((v0 - mean) * r * w[t] + b[t]);
    o[t + 256] = tf32f_((v1 - mean) * r * w[t + 256] + b[t + 256]);
}

// ---------------- output layernorm: g_attn (L,256) -> g_y (tf32-rounded) ----------------
__global__ void k_ln_out(const float* __restrict__ w, const float* __restrict__ b, int L) {
    int row = blockIdx.x;
    int t = threadIdx.x;
    float v = g_attn[(size_t)row * 256 + t];
    float s = v, ss = v * v;
#pragma unroll
    for (int o = 16; o; o >>= 1) {
        s += __shfl_xor_sync(0xffffffffu, s, o);
        ss += __shfl_xor_sync(0xffffffffu, ss, o);
    }
    __shared__ float shs[8], shss[8];
    if ((t & 31) == 0) { shs[t >> 5] = s; shss[t >> 5] = ss; }
    __syncthreads();
    s = 0.f; ss = 0.f;
#pragma unroll
    for (int i = 0; i < 8; i++) { s += shs[i]; ss += shss[i]; }
    float mean = s * (1.0f / 256.0f);
    float var = ss * (1.0f / 256.0f) - mean * mean;
    float r = rsqrtf(var + 1e-6f);
    g_y[(size_t)row * 256 + t] = tf32f_((v - mean) * r * w[t] + b[t]);
}

// ---------------- GEMM core constants ----------------
#define AS_PITCH 36
#define BS_PITCH 136
#define AS_WORDS (128 * AS_PITCH)
#define BS_WORDS (32 * BS_PITCH)
#define GEMM_SMEM ((2 * (AS_WORDS + BS_WORDS)) * 4)

// ---------------- GEMM1: g_uvqk = silu(g_nx @ W(512x1024) + bias), tf32-rounded ----------------
__global__ __launch_bounds__(256) void k_gemm1_tc(const float* __restrict__ W,
                                                  const float* __restrict__ bias, int L) {
    extern __shared__ unsigned smu[];
    unsigned* AsB = smu;
    unsigned* BsB = smu + 2 * AS_WORDS;
    int tid = threadIdx.x, lane = tid & 31, wid = tid >> 5;
    int wm = wid >> 2, wn = wid & 3;
    int l4 = lane >> 2, l3 = lane & 3;
    int row0 = blockIdx.y * 128, col0 = blockIdx.x * 128;

    float acc[4][4][4];
#pragma unroll
    for (int i = 0; i < 4; i++)
#pragma unroll
        for (int j = 0; j < 4; j++)
#pragma unroll
            for (int q = 0; q < 4; q++) acc[i][j][q] = 0.f;

    int ar_r = tid >> 3, ar_c = (tid & 7) * 4;
    int br_r = tid >> 5, br_c = (tid & 31) * 4;

    auto prefetch = [&](int k0, int st) {
        unsigned* As = AsB + st * AS_WORDS;
        unsigned* Bs = BsB + st * BS_WORDS;
#pragma unroll
        for (int p = 0; p < 4; p++) {
            int gr = min(row0 + ar_r + p * 32, L - 1);
            cpa16(&As[(ar_r + p * 32) * AS_PITCH + ar_c],
                  g_nx + (size_t)gr * 512 + k0 + ar_c);
            cpa16(&Bs[(br_r + p * 8) * BS_PITCH + br_c],
                  W + (size_t)(k0 + br_r + p * 8) * 1024 + col0 + br_c);
        }
        CP_COMMIT;
    };
    auto compute = [&](int st) {
        unsigned* As = AsB + st * AS_WORDS;
        unsigned* Bs = BsB + st * BS_WORDS;
#pragma unroll
        for (int kk = 0; kk < 32; kk += 8) {
            unsigned b0[4], b1[4];
#pragma unroll
            for (int nt = 0; nt < 4; nt++) {
                int bc = wn * 32 + nt * 8 + l4;
                b0[nt] = Bs[(kk + l3) * BS_PITCH + bc];
                b1[nt] = Bs[(kk + l3 + 4) * BS_PITCH + bc];
            }
#pragma unroll
            for (int mt = 0; mt < 4; mt++) {
                int ar = wm * 64 + mt * 16 + l4;
                unsigned a0 = As[ar * AS_PITCH + kk + l3];
                unsigned a1 = As[(ar + 8) * AS_PITCH + kk + l3];
                unsigned a2 = As[ar * AS_PITCH + kk + l3 + 4];
                unsigned a3 = As[(ar + 8) * AS_PITCH + kk + l3 + 4];
#pragma unroll
                for (int nt = 0; nt < 4; nt++)
                    mma8(acc[mt][nt], a0, a1, a2, a3, b0[nt], b1[nt]);
            }
        }
    };

    prefetch(0, 0);
    CP_WAIT0;
    __syncthreads();
    int cur = 0;
    for (int k0 = 0; k0 < 512; k0 += 32) {
        if (k0 + 32 < 512) prefetch(k0 + 32, cur ^ 1);
        compute(cur);
        if (k0 + 32 < 512) {
            CP_WAIT0;
            __syncthreads();
            cur ^= 1;
        }
    }

#pragma unroll
    for (int mt = 0; mt < 4; mt++)
#pragma unroll
        for (int nt = 0; nt < 4; nt++) {
            int r = row0 + wm * 64 + mt * 16 + l4;
            int c = col0 + wn * 32 + nt * 8 + l3 * 2;
            float2 bb = *(const float2*)(bias + c);
            if (r < L) {
                float2 o;
                o.x = tf32f_(silu_(acc[mt][nt][0] + bb.x));
                o.y = tf32f_(silu_(acc[mt][nt][1] + bb.y));
                *(float2*)(g_uvqk + (size_t)r * 1024 + c) = o;
            }
            if (r + 8 < L) {
                float2 o;
                o.x = tf32f_(silu_(acc[mt][nt][2] + bb.x));
                o.y = tf32f_(silu_(acc[mt][nt][3] + bb.y));
                *(float2*)(g_uvqk + (size_t)(r + 8) * 1024 + c) = o;
            }
        }
}

// ---------------- GEMM2: out = x + [u|x|y] @ Wout(1024x512) ----------------
__global__ __launch_bounds__(256) void k_gemm2_tc(const float* __restrict__ x,
                                                  const float* __restrict__ Wout, int L,
                                                  float* __restrict__ out) {
    extern __shared__ unsigned smu[];
    unsigned* AsB = smu;
    unsigned* BsB = smu + 2 * AS_WORDS;
    int tid = threadIdx.x, lane = tid & 31, wid = tid >> 5;
    int wm = wid >> 2, wn = wid & 3;
    int l4 = lane >> 2, l3 = lane & 3;
    int row0 = blockIdx.y * 128, col0 = blockIdx.x * 128;

    float acc[4][4][4];
#pragma unroll
    for (int i = 0; i < 4; i++)
#pragma unroll
        for (int j = 0; j < 4; j++)
#pragma unroll
            for (int q = 0; q < 4; q++) acc[i][j][q] = 0.f;

    int ar_r = tid >> 3, ar_c = (tid & 7) * 4;
    int br_r = tid >> 5, br_c = (tid & 31) * 4;

    auto prefetch = [&](int k0, int st) {
        unsigned* As = AsB + st * AS_WORDS;
        unsigned* Bs = BsB + st * BS_WORDS;
        int j = k0 + ar_c;
        const float* base;
        int pitch;
        if (j < 256) { base = g_uvqk + j; pitch = 1024; }
        else if (j < 768) { base = x + (j - 256); pitch = 512; }
        else { base = g_y + (j - 768); pitch = 256; }
#pragma unroll
        for (int p = 0; p < 4; p++) {
            int gr = min(row0 + ar_r + p * 32, L - 1);
            cpa16(&As[(ar_r + p * 32) * AS_PITCH + ar_c], base + (size_t)gr * pitch);
            cpa16(&Bs[(br_r + p * 8) * BS_PITCH + br_c],
                  Wout + (size_t)(k0 + br_r + p * 8) * 512 + col0 + br_c);
        }
        CP_COMMIT;
    };
    auto compute = [&](int st) {
        unsigned* As = AsB + st * AS_WORDS;
        unsigned* Bs = BsB + st * BS_WORDS;
#pragma unroll
        for (int kk = 0; kk < 32; kk += 8) {
            unsigned b0[4], b1[4];
#pragma unroll
            for (int nt = 0; nt < 4; nt++) {
                int bc = wn * 32 + nt * 8 + l4;
                b0[nt] = Bs[(kk + l3) * BS_PITCH + bc];
                b1[nt] = Bs[(kk + l3 + 4) * BS_PITCH + bc];
            }
#pragma unroll
            for (int mt = 0; mt < 4; mt++) {
                int ar = wm * 64 + mt * 16 + l4;
                unsigned a0 = As[ar * AS_PITCH + kk + l3];
                unsigned a1 = As[(ar + 8) * AS_PITCH + kk + l3];
                unsigned a2 = As[ar * AS_PITCH + kk + l3 + 4];
                unsigned a3 = As[(ar + 8) * AS_PITCH + kk + l3 + 4];
#pragma unroll
                for (int nt = 0; nt < 4; nt++)
                    mma8(acc[mt][nt], a0, a1, a2, a3, b0[nt], b1[nt]);
            }
        }
    };

    prefetch(0, 0);
    CP_WAIT0;
    __syncthreads();
    int cur = 0;
    for (int k0 = 0; k0 < 1024; k0 += 32) {
        if (k0 + 32 < 1024) prefetch(k0 + 32, cur ^ 1);
        compute(cur);
        if (k0 + 32 < 1024) {
            CP_WAIT0;
            __syncthreads();
            cur ^= 1;
        }
    }

#pragma unroll
    for (int mt = 0; mt < 4; mt++)
#pragma unroll
        for (int nt = 0; nt < 4; nt++) {
            int r = row0 + wm * 64 + mt * 16 + l4;
            int c = col0 + wn * 32 + nt * 8 + l3 * 2;
            if (r < L) {
                float2 xv = *(const float2*)(x + (size_t)r * 512 + c);
                float2 o;
                o.x = xv.x + acc[mt][nt][0];
                o.y = xv.y + acc[mt][nt][1];
                *(float2*)(out + (size_t)r * 512 + c) = o;
            }
            if (r + 8 < L) {
                float2 xv = *(const float2*)(x + (size_t)(r + 8) * 512 + c);
                float2 o;
                o.x = xv.x + acc[mt][nt][2];
                o.y = xv.y + acc[mt][nt][3];
                *(float2*)(out + (size_t)(r + 8) * 512 + c) = o;
            }
        }
}

// ---------------- attention (tensor core tf32, cp.async double-buffered K/V) ----------------
// smem words: [0,4352) QSs (Q tf32, later S f32, pitch 68)
//             [4352, 4352+2*4352) Ks stages (pitch 68)
//             [13056, 13056+2*4608) Vs stages (pitch 72)
#define ATT_QS 0
#define ATT_KS 4352
#define ATT_KS_W 4352
#define ATT_VS 13056
#define ATT_VS_W 4608
#define ATT_SMEM ((13056 + 2 * 4608) * 4)

__global__ __launch_bounds__(256) void k_attn_tc(const int* __restrict__ lengths,
                                                 const int* __restrict__ offsets,
                                                 const int* __restrict__ ntargets,
                                                 const int* __restrict__ msl, int TPB) {
    extern __shared__ unsigned smu[];
    unsigned(*QSs)[68] = (unsigned(*)[68])(smu + ATT_QS);
    float(*Ss)[68] = (float(*)[68])(smu + ATT_QS);  // alias: Q consumed before S written

    int h = blockIdx.y;
    int b = blockIdx.x / TPB;
    int t = blockIdx.x % TPB;
    int len = lengths[b];
    int q0 = t * 64;
    if (q0 >= len) return;
    int off = offsets[b];
    int lim = len - ntargets[b];
    float invN = 1.0f / (float)msl[0];

    int tid = threadIdx.x, lane = tid & 31, wid = tid >> 5;
    int wm = wid >> 1, wn = wid & 1;
    int l4 = lane >> 2, l3 = lane & 3;
    int lr = tid >> 2, lc0 = (tid & 3) * 16;

    const uint4 zero4 = make_uint4(0u, 0u, 0u, 0u);

    auto prefetchKV = [&](int m0, int st) {
        int m = m0 + lr;
        bool ok = m < len;
        const float* kp =
            g_uvqk + (size_t)(off + min(m, len - 1)) * 1024 + 768 + h * 64 + lc0;
        const float* vp = kp - 512;  // v segment at 256
        unsigned* Kst = smu + ATT_KS + st * ATT_KS_W;
        unsigned* Vst = smu + ATT_VS + st * ATT_VS_W;
#pragma unroll
        for (int i = 0; i < 4; i++) {
            cpa16z(&Kst[lr * 68 + lc0 + i * 4], kp + i * 4, ok);
            cpa16z(&Vst[lr * 72 + lc0 + i * 4], vp + i * 4, ok);
        }
        CP_COMMIT;
    };

    // ---- prologue: prefetch tile 0, load Q plain ----
    prefetchKV(0, 0);
    {
        int n = q0 + lr;
        const uint4* qp = (const uint4*)(g_uvqk + (size_t)(off + min(n, len - 1)) * 1024 +
                                         512 + h * 64 + lc0);
        bool ok = n < len;
#pragma unroll
        for (int i = 0; i < 4; i++)
            *(uint4*)&QSs[lr][lc0 + i * 4] = ok ? qp[i] : zero4;
    }
    __syncthreads();

    unsigned qf[8][4];
#pragma unroll
    for (int ks = 0; ks < 8; ks++) {
        qf[ks][0] = QSs[wm * 16 + l4][ks * 8 + l3];
        qf[ks][1] = QSs[wm * 16 + l4 + 8][ks * 8 + l3];
        qf[ks][2] = QSs[wm * 16 + l4][ks * 8 + l3 + 4];
        qf[ks][3] = QSs[wm * 16 + l4 + 8][ks * 8 + l3 + 4];
    }

    float oacc[4][4];
#pragma unroll
    for (int i = 0; i < 4; i++)
#pragma unroll
        for (int j = 0; j < 4; j++) oacc[i][j] = 0.f;

    int nIter = q0 / 64 + 1;
    int cur = 0;
    for (int it = 0; it < nIter; it++) {
        CP_WAIT0;        // this iter's K/V copies done (per-thread)
        __syncthreads(); // block-wide visibility; also: all qf reads (it==0) / prior
                         // PV S-reads done before S overwritten below
        const unsigned* Kst = smu + ATT_KS + cur * ATT_KS_W;
        const unsigned* Vst = smu + ATT_VS + cur * ATT_VS_W;

        // ---- QK^T ----
        float sacc[4][4];
#pragma unroll
        for (int i = 0; i < 4; i++)
#pragma unroll
            for (int j = 0; j < 4; j++) sacc[i][j] = 0.f;
#pragma unroll
        for (int ks = 0; ks < 8; ks++) {
            unsigned b0[4], b1[4];
#pragma unroll
            for (int nt = 0; nt < 4; nt++) {
                int mr = wn * 32 + nt * 8 + l4;
                b0[nt] = Kst[mr * 68 + ks * 8 + l3];
                b1[nt] = Kst[mr * 68 + ks * 8 + l3 + 4];
            }
#pragma unroll
            for (int nt = 0; nt < 4; nt++)
                mma8(sacc[nt], qf[ks][0], qf[ks][1], qf[ks][2], qf[ks][3], b0[nt], b1[nt]);
        }

        // ---- silu + mask, store S ----
        int m0 = it * 64;
        {
            int n_lo = q0 + wm * 16 + l4;
            int n_hi = n_lo + 8;
            int idn_lo = min(n_lo, lim), idn_hi = min(n_hi, lim);
            bool nok_lo = n_lo < len, nok_hi = n_hi < len;
#pragma unroll
            for (int nt = 0; nt < 4; nt++) {
                int m_ = m0 + wn * 32 + nt * 8 + 2 * l3;
#pragma unroll
                for (int jj = 0; jj < 2; jj++) {
                    int m = m_ + jj;
                    int idm = min(m, lim);
                    bool mok = m < len;
                    float z0 = sacc[nt][jj] * 0.125f;
                    float w0 = silu_(z0) * invN;
                    bool ok0 = mok && nok_lo && ((idn_lo > idm) || (n_lo == m));
                    sacc[nt][jj] = ok0 ? w0 : 0.f;
                    float z1 = sacc[nt][jj + 2] * 0.125f;
                    float w1 = silu_(z1) * invN;
                    bool ok1 = mok && nok_hi && ((idn_hi > idm) || (n_hi == m));
                    sacc[nt][jj + 2] = ok1 ? w1 : 0.f;
                }
                int sr = wm * 16 + l4;
                int sc = wn * 32 + nt * 8 + 2 * l3;
                *(float2*)&Ss[sr][sc] = make_float2(sacc[nt][0], sacc[nt][1]);
                *(float2*)&Ss[sr + 8][sc] = make_float2(sacc[nt][2], sacc[nt][3]);
            }
        }
        __syncthreads();  // S visible; all of iter it-1 complete block-wide

        // ---- prefetch next tile into the other stage (overlaps PV + next QK) ----
        if (it + 1 < nIter) prefetchKV(m0 + 64, cur ^ 1);

        // ---- PV ----
#pragma unroll
        for (int km = 0; km < 8; km++) {
            unsigned a0 = __float_as_uint(Ss[wm * 16 + l4][km * 8 + l3]);
            unsigned a1 = __float_as_uint(Ss[wm * 16 + l4 + 8][km * 8 + l3]);
            unsigned a2 = __float_as_uint(Ss[wm * 16 + l4][km * 8 + l3 + 4]);
            unsigned a3 = __float_as_uint(Ss[wm * 16 + l4 + 8][km * 8 + l3 + 4]);
#pragma unroll
            for (int nt = 0; nt < 4; nt++) {
                unsigned b0 = Vst[(km * 8 + l3) * 72 + wn * 32 + nt * 8 + l4];
                unsigned b1 = Vst[(km * 8 + l3 + 4) * 72 + wn * 32 + nt * 8 + l4];
                mma8(oacc[nt], a0, a1, a2, a3, b0, b1);
            }
        }
        cur ^= 1;
    }

#pragma unroll
    for (int nt = 0; nt < 4; nt++) {
        int col = h * 64 + wn * 32 + nt * 8 + 2 * l3;
        int n = q0 + wm * 16 + l4;
        if (n < len)
            *(float2*)&g_attn[(size_t)(off + n) * 256 + col] =
                make_float2(oacc[nt][0], oacc[nt][1]);
        if (n + 8 < len)
            *(float2*)&g_attn[(size_t)(off + n + 8) * 256 + col] =
                make_float2(oacc[nt][2], oacc[nt][3]);
    }
}

extern "C" void kernel_launch(void* const* d_in, const int* in_sizes, int n_in,
                              void* d_out, int out_size) {
    const float* x = (const float*)d_in[0];
    const int* xl = (const int*)d_in[1];
    const int* xo = (const int*)d_in[2];
    const int* msl = (const int*)d_in[3];
    const int* nt = (const int*)d_in[4];
    const float* Wu = (const float*)d_in[5];
    const float* bu = (const float*)d_in[6];
    const float* inw = (const float*)d_in[7];
    const float* inb = (const float*)d_in[8];
    const float* onw = (const float*)d_in[9];
    const float* onb = (const float*)d_in[10];
    const float* Wo = (const float*)d_in[11];
    float* out = (float*)d_out;

    int L = in_sizes[0] / 512;
    int B = in_sizes[1];

    static bool attr_set = false;
    if (!attr_set) {
        cudaFuncSetAttribute(k_attn_tc, cudaFuncAttributeMaxDynamicSharedMemorySize,
                             ATT_SMEM);
        cudaFuncSetAttribute(k_gemm1_tc, cudaFuncAttributeMaxDynamicSharedMemorySize,
                             GEMM_SMEM);
        cudaFuncSetAttribute(k_gemm2_tc, cudaFuncAttributeMaxDynamicSharedMemorySize,
                             GEMM_SMEM);
        attr_set = true;
    }

    k_ln_in<<<L, 256>>>(x, inw, inb, L);

    dim3 g1(1024 / 128, (L + 127) / 128);
    k_gemm1_tc<<<g1, 256, GEMM_SMEM>>>(Wu, bu, L);

    int TPB = (L + 63) / 64;
    dim3 ga(B * TPB, HH);
    k_attn_tc<<<ga, 256, ATT_SMEM>>>(xl, xo, nt, msl, TPB);

    k_ln_out<<<L, 256>>>(onw, onb, L);

    dim3 g2(512 / 128, (L + 127) / 128);
    k_gemm2_tc<<<g2, 256, GEMM_SMEM>>>(x, Wo, L, out);
}

// round 11
// speedup vs baseline: 3.4320x; 1.1100x over previous
#include <cuda_runtime.h>
#include <math.h>

#define LMAX 8192
#define HH 4

__device__ float g_nx[LMAX * 512];    // tf32-rounded
__device__ float g_uvqk[LMAX * 1024]; // tf32-rounded
__device__ float g_attn[LMAX * 256];  // fp32
__device__ float g_y[LMAX * 256];     // tf32-rounded

__device__ __forceinline__ float silu_(float z) {
    return z / (1.0f + __expf(-z));
}

__device__ __forceinline__ float tanh_(float x) {
    float r;
    asm("tanh.approx.f32 %0, %1;" : "=f"(r) : "f"(x));
    return r;
}

__device__ __forceinline__ unsigned tf32_(float f) {
    unsigned r;
    asm("cvt.rna.tf32.f32 %0, %1;" : "=r"(r) : "f"(f));
    return r;
}

__device__ __forceinline__ float tf32f_(float f) {
    return __uint_as_float(tf32_(f));
}

__device__ __forceinline__ void mma8(float* d, unsigned a0, unsigned a1, unsigned a2,
                                     unsigned a3, unsigned b0, unsigned b1) {
    asm volatile(
        "mma.sync.aligned.m16n8k8.row.col.f32.tf32.tf32.f32 "
        "{%0,%1,%2,%3}, {%4,%5,%6,%7}, {%8,%9}, {%0,%1,%2,%3};\n"
        : "+f"(d[0]), "+f"(d[1]), "+f"(d[2]), "+f"(d[3])
        : "r"(a0), "r"(a1), "r"(a2), "r"(a3), "r"(b0), "r"(b1));
}

__device__ __forceinline__ void cpa16(void* s, const void* g) {
    unsigned sa = (unsigned)__cvta_generic_to_shared(s);
    asm volatile("cp.async.cg.shared.global [%0], [%1], 16;" ::"r"(sa), "l"(g));
}
__device__ __forceinline__ void cpa16z(void* s, const void* g, bool ok) {
    unsigned sa = (unsigned)__cvta_generic_to_shared(s);
    int sz = ok ? 16 : 0;
    asm volatile("cp.async.cg.shared.global [%0], [%1], 16, %2;" ::"r"(sa), "l"(g),
                 "r"(sz));
}
#define CP_COMMIT asm volatile("cp.async.commit_group;")
#define CP_WAIT0 asm volatile("cp.async.wait_group 0;")

// ---------------- input layernorm: warp per row, (L,512) -> g_nx ----------------
__global__ __launch_bounds__(256) void k_ln_in(const float* __restrict__ x,
                                               const float* __restrict__ w,
                                               const float* __restrict__ b, int L) {
    int row = blockIdx.x * 8 + (threadIdx.x >> 5);
    if (row >= L) return;
    int lane = threadIdx.x & 31;
    const float4* xr = (const float4*)(x + (size_t)row * 512);
    float4 v[4];
    float s = 0.f, ss = 0.f;
#pragma unroll
    for (int i = 0; i < 4; i++) {
        v[i] = xr[lane + 32 * i];
        s += v[i].x + v[i].y + v[i].z + v[i].w;
        ss += v[i].x * v[i].x + v[i].y * v[i].y + v[i].z * v[i].z + v[i].w * v[i].w;
    }
#pragma unroll
    for (int o = 16; o; o >>= 1) {
        s += __shfl_xor_sync(0xffffffffu, s, o);
        ss += __shfl_xor_sync(0xffffffffu, ss, o);
    }
    float mean = s * (1.0f / 512.0f);
    float var = ss * (1.0f / 512.0f) - mean * mean;
    float r = rsqrtf(var + 1e-6f);
    float4* o = (float4*)(g_nx + (size_t)row * 512);
    const float4* wp = (const float4*)w;
    const float4* bp = (const float4*)b;
#pragma unroll
    for (int i = 0; i < 4; i++) {
        float4 wv = wp[lane + 32 * i], bv = bp[lane + 32 * i];
        float4 ov;
        ov.x = tf32f_((v[i].x - mean) * r * wv.x + bv.x);
        ov.y = tf32f_((v[i].y - mean) * r * wv.y + bv.y);
        ov.z = tf32f_((v[i].z - mean) * r * wv.z + bv.z);
        ov.w = tf32f_((v[i].w - mean) * r * wv.w + bv.w);
        o[lane + 32 * i] = ov;
    }
}

// ---------------- output layernorm: warp per row, g_attn (L,256) -> g_y ----------------
__global__ __launch_bounds__(256) void k_ln_out(const float* __restrict__ w,
                                                const float* __restrict__ b, int L) {
    int row = blockIdx.x * 8 + (threadIdx.x >> 5);
    if (row >= L) return;
    int lane = threadIdx.x & 31;
    const float4* xr = (const float4*)(g_attn + (size_t)row * 256);
    float4 v[2];
    float s = 0.f, ss = 0.f;
#pragma unroll
    for (int i = 0; i < 2; i++) {
        v[i] = xr[lane + 32 * i];
        s += v[i].x + v[i].y + v[i].z + v[i].w;
        ss += v[i].x * v[i].x + v[i].y * v[i].y + v[i].z * v[i].z + v[i].w * v[i].w;
    }
#pragma unroll
    for (int o = 16; o; o >>= 1) {
        s += __shfl_xor_sync(0xffffffffu, s, o);
        ss += __shfl_xor_sync(0xffffffffu, ss, o);
    }
    float mean = s * (1.0f / 256.0f);
    float var = ss * (1.0f / 256.0f) - mean * mean;
    float r = rsqrtf(var + 1e-6f);
    float4* o = (float4*)(g_y + (size_t)row * 256);
    const float4* wp = (const float4*)w;
    const float4* bp = (const float4*)b;
#pragma unroll
    for (int i = 0; i < 2; i++) {
        float4 wv = wp[lane + 32 * i], bv = bp[lane + 32 * i];
        float4 ov;
        ov.x = tf32f_((v[i].x - mean) * r * wv.x + bv.x);
        ov.y = tf32f_((v[i].y - mean) * r * wv.y + bv.y);
        ov.z = tf32f_((v[i].z - mean) * r * wv.z + bv.z);
        ov.w = tf32f_((v[i].w - mean) * r * wv.w + bv.w);
        o[lane + 32 * i] = ov;
    }
}

// ---------------- GEMM core constants ----------------
#define AS_PITCH 36
#define BS_PITCH 136
#define AS_WORDS (128 * AS_PITCH)
#define BS_WORDS (32 * BS_PITCH)
#define GEMM_SMEM ((2 * (AS_WORDS + BS_WORDS)) * 4)

// ---------------- GEMM1: g_uvqk = silu(g_nx @ W(512x1024) + bias), tf32-rounded ----------------
__global__ __launch_bounds__(256) void k_gemm1_tc(const float* __restrict__ W,
                                                  const float* __restrict__ bias, int L) {
    extern __shared__ unsigned smu[];
    unsigned* AsB = smu;
    unsigned* BsB = smu + 2 * AS_WORDS;
    int tid = threadIdx.x, lane = tid & 31, wid = tid >> 5;
    int wm = wid >> 2, wn = wid & 3;
    int l4 = lane >> 2, l3 = lane & 3;
    int row0 = blockIdx.y * 128, col0 = blockIdx.x * 128;

    float acc[4][4][4];
#pragma unroll
    for (int i = 0; i < 4; i++)
#pragma unroll
        for (int j = 0; j < 4; j++)
#pragma unroll
            for (int q = 0; q < 4; q++) acc[i][j][q] = 0.f;

    int ar_r = tid >> 3, ar_c = (tid & 7) * 4;
    int br_r = tid >> 5, br_c = (tid & 31) * 4;

    auto prefetch = [&](int k0, int st) {
        unsigned* As = AsB + st * AS_WORDS;
        unsigned* Bs = BsB + st * BS_WORDS;
#pragma unroll
        for (int p = 0; p < 4; p++) {
            int gr = min(row0 + ar_r + p * 32, L - 1);
            cpa16(&As[(ar_r + p * 32) * AS_PITCH + ar_c],
                  g_nx + (size_t)gr * 512 + k0 + ar_c);
            cpa16(&Bs[(br_r + p * 8) * BS_PITCH + br_c],
                  W + (size_t)(k0 + br_r + p * 8) * 1024 + col0 + br_c);
        }
        CP_COMMIT;
    };
    auto compute = [&](int st) {
        unsigned* As = AsB + st * AS_WORDS;
        unsigned* Bs = BsB + st * BS_WORDS;
#pragma unroll
        for (int kk = 0; kk < 32; kk += 8) {
            unsigned b0[4], b1[4];
#pragma unroll
            for (int nt = 0; nt < 4; nt++) {
                int bc = wn * 32 + nt * 8 + l4;
                b0[nt] = Bs[(kk + l3) * BS_PITCH + bc];
                b1[nt] = Bs[(kk + l3 + 4) * BS_PITCH + bc];
            }
#pragma unroll
            for (int mt = 0; mt < 4; mt++) {
                int ar = wm * 64 + mt * 16 + l4;
                unsigned a0 = As[ar * AS_PITCH + kk + l3];
                unsigned a1 = As[(ar + 8) * AS_PITCH + kk + l3];
                unsigned a2 = As[ar * AS_PITCH + kk + l3 + 4];
                unsigned a3 = As[(ar + 8) * AS_PITCH + kk + l3 + 4];
#pragma unroll
                for (int nt = 0; nt < 4; nt++)
                    mma8(acc[mt][nt], a0, a1, a2, a3, b0[nt], b1[nt]);
            }
        }
    };

    prefetch(0, 0);
    CP_WAIT0;
    __syncthreads();
    int cur = 0;
    for (int k0 = 0; k0 < 512; k0 += 32) {
        if (k0 + 32 < 512) prefetch(k0 + 32, cur ^ 1);
        compute(cur);
        if (k0 + 32 < 512) {
            CP_WAIT0;
            __syncthreads();
            cur ^= 1;
        }
    }

#pragma unroll
    for (int mt = 0; mt < 4; mt++)
#pragma unroll
        for (int nt = 0; nt < 4; nt++) {
            int r = row0 + wm * 64 + mt * 16 + l4;
            int c = col0 + wn * 32 + nt * 8 + l3 * 2;
            float2 bb = *(const float2*)(bias + c);
            if (r < L) {
                float2 o;
                o.x = tf32f_(silu_(acc[mt][nt][0] + bb.x));
                o.y = tf32f_(silu_(acc[mt][nt][1] + bb.y));
                *(float2*)(g_uvqk + (size_t)r * 1024 + c) = o;
            }
            if (r + 8 < L) {
                float2 o;
                o.x = tf32f_(silu_(acc[mt][nt][2] + bb.x));
                o.y = tf32f_(silu_(acc[mt][nt][3] + bb.y));
                *(float2*)(g_uvqk + (size_t)(r + 8) * 1024 + c) = o;
            }
        }
}

// ---------------- GEMM2: out = x + [u|x|y] @ Wout(1024x512) ----------------
__global__ __launch_bounds__(256) void k_gemm2_tc(const float* __restrict__ x,
                                                  const float* __restrict__ Wout, int L,
                                                  float* __restrict__ out) {
    extern __shared__ unsigned smu[];
    unsigned* AsB = smu;
    unsigned* BsB = smu + 2 * AS_WORDS;
    int tid = threadIdx.x, lane = tid & 31, wid = tid >> 5;
    int wm = wid >> 2, wn = wid & 3;
    int l4 = lane >> 2, l3 = lane & 3;
    int row0 = blockIdx.y * 128, col0 = blockIdx.x * 128;

    float acc[4][4][4];
#pragma unroll
    for (int i = 0; i < 4; i++)
#pragma unroll
        for (int j = 0; j < 4; j++)
#pragma unroll
            for (int q = 0; q < 4; q++) acc[i][j][q] = 0.f;

    int ar_r = tid >> 3, ar_c = (tid & 7) * 4;
    int br_r = tid >> 5, br_c = (tid & 31) * 4;

    auto prefetch = [&](int k0, int st) {
        unsigned* As = AsB + st * AS_WORDS;
        unsigned* Bs = BsB + st * BS_WORDS;
        int j = k0 + ar_c;
        const float* base;
        int pitch;
        if (j < 256) { base = g_uvqk + j; pitch = 1024; }
        else if (j < 768) { base = x + (j - 256); pitch = 512; }
        else { base = g_y + (j - 768); pitch = 256; }
#pragma unroll
        for (int p = 0; p < 4; p++) {
            int gr = min(row0 + ar_r + p * 32, L - 1);
            cpa16(&As[(ar_r + p * 32) * AS_PITCH + ar_c], base + (size_t)gr * pitch);
            cpa16(&Bs[(br_r + p * 8) * BS_PITCH + br_c],
                  Wout + (size_t)(k0 + br_r + p * 8) * 512 + col0 + br_c);
        }
        CP_COMMIT;
    };
    auto compute = [&](int st) {
        unsigned* As = AsB + st * AS_WORDS;
        unsigned* Bs = BsB + st * BS_WORDS;
#pragma unroll
        for (int kk = 0; kk < 32; kk += 8) {
            unsigned b0[4], b1[4];
#pragma unroll
            for (int nt = 0; nt < 4; nt++) {
                int bc = wn * 32 + nt * 8 + l4;
                b0[nt] = Bs[(kk + l3) * BS_PITCH + bc];
                b1[nt] = Bs[(kk + l3 + 4) * BS_PITCH + bc];
            }
#pragma unroll
            for (int mt = 0; mt < 4; mt++) {
                int ar = wm * 64 + mt * 16 + l4;
                unsigned a0 = As[ar * AS_PITCH + kk + l3];
                unsigned a1 = As[(ar + 8) * AS_PITCH + kk + l3];
                unsigned a2 = As[ar * AS_PITCH + kk + l3 + 4];
                unsigned a3 = As[(ar + 8) * AS_PITCH + kk + l3 + 4];
#pragma unroll
                for (int nt = 0; nt < 4; nt++)
                    mma8(acc[mt][nt], a0, a1, a2, a3, b0[nt], b1[nt]);
            }
        }
    };

    prefetch(0, 0);
    CP_WAIT0;
    __syncthreads();
    int cur = 0;
    for (int k0 = 0; k0 < 1024; k0 += 32) {
        if (k0 + 32 < 1024) prefetch(k0 + 32, cur ^ 1);
        compute(cur);
        if (k0 + 32 < 1024) {
            CP_WAIT0;
            __syncthreads();
            cur ^= 1;
        }
    }

#pragma unroll
    for (int mt = 0; mt < 4; mt++)
#pragma unroll
        for (int nt = 0; nt < 4; nt++) {
            int r = row0 + wm * 64 + mt * 16 + l4;
            int c = col0 + wn * 32 + nt * 8 + l3 * 2;
            if (r < L) {
                float2 xv = *(const float2*)(x + (size_t)r * 512 + c);
                float2 o;
                o.x = xv.x + acc[mt][nt][0];
                o.y = xv.y + acc[mt][nt][1];
                *(float2*)(out + (size_t)r * 512 + c) = o;
            }
            if (r + 8 < L) {
                float2 xv = *(const float2*)(x + (size_t)(r + 8) * 512 + c);
                float2 o;
                o.x = xv.x + acc[mt][nt][2];
                o.y = xv.y + acc[mt][nt][3];
                *(float2*)(out + (size_t)(r + 8) * 512 + c) = o;
            }
        }
}

// ---------------- attention (tensor core tf32, cp.async double-buffered K/V) ----------------
#define ATT_QS 0
#define ATT_KS 4352
#define ATT_KS_W 4352
#define ATT_VS 13056
#define ATT_VS_W 4608
#define ATT_SMEM ((13056 + 2 * 4608) * 4)

__global__ __launch_bounds__(256) void k_attn_tc(const int* __restrict__ lengths,
                                                 const int* __restrict__ offsets,
                                                 const int* __restrict__ ntargets,
                                                 const int* __restrict__ msl, int TPB) {
    extern __shared__ unsigned smu[];
    unsigned(*QSs)[68] = (unsigned(*)[68])(smu + ATT_QS);
    float(*Ss)[68] = (float(*)[68])(smu + ATT_QS);  // alias: Q consumed before S written

    int h = blockIdx.y;
    int b = blockIdx.x / TPB;
    int t = blockIdx.x % TPB;
    int len = lengths[b];
    int q0 = t * 64;
    if (q0 >= len) return;
    int off = offsets[b];
    int lim = len - ntargets[b];
    float invN = 1.0f / (float)msl[0];
    float c1 = 0.125f * invN;  // z*invN = s*c1

    int tid = threadIdx.x, lane = tid & 31, wid = tid >> 5;
    int wm = wid >> 1, wn = wid & 1;
    int l4 = lane >> 2, l3 = lane & 3;
    int lr = tid >> 2, lc0 = (tid & 3) * 16;

    const uint4 zero4 = make_uint4(0u, 0u, 0u, 0u);

    auto prefetchKV = [&](int m0, int st) {
        int m = m0 + lr;
        bool ok = m < len;
        const float* kp =
            g_uvqk + (size_t)(off + min(m, len - 1)) * 1024 + 768 + h * 64 + lc0;
        const float* vp = kp - 512;  // v segment at 256
        unsigned* Kst = smu + ATT_KS + st * ATT_KS_W;
        unsigned* Vst = smu + ATT_VS + st * ATT_VS_W;
#pragma unroll
        for (int i = 0; i < 4; i++) {
            cpa16z(&Kst[lr * 68 + lc0 + i * 4], kp + i * 4, ok);
            cpa16z(&Vst[lr * 72 + lc0 + i * 4], vp + i * 4, ok);
        }
        CP_COMMIT;
    };

    prefetchKV(0, 0);
    {
        int n = q0 + lr;
        const uint4* qp = (const uint4*)(g_uvqk + (size_t)(off + min(n, len - 1)) * 1024 +
                                         512 + h * 64 + lc0);
        bool ok = n < len;
#pragma unroll
        for (int i = 0; i < 4; i++)
            *(uint4*)&QSs[lr][lc0 + i * 4] = ok ? qp[i] : zero4;
    }
    __syncthreads();

    unsigned qf[8][4];
#pragma unroll
    for (int ks = 0; ks < 8; ks++) {
        qf[ks][0] = QSs[wm * 16 + l4][ks * 8 + l3];
        qf[ks][1] = QSs[wm * 16 + l4 + 8][ks * 8 + l3];
        qf[ks][2] = QSs[wm * 16 + l4][ks * 8 + l3 + 4];
        qf[ks][3] = QSs[wm * 16 + l4 + 8][ks * 8 + l3 + 4];
    }

    float oacc[4][4];
#pragma unroll
    for (int i = 0; i < 4; i++)
#pragma unroll
        for (int j = 0; j < 4; j++) oacc[i][j] = 0.f;

    int nIter = q0 / 64 + 1;
    int cur = 0;
    for (int it = 0; it < nIter; it++) {
        int m0 = it * 64;
        CP_WAIT0;        // this iter's K/V copies landed (issuing thread)
        __syncthreads(); // block-wide visibility; all reads of stage cur^1 (iter it-1) done
        // prefetch next tile now — overlaps QK + silu + PV of this iter
        if (it + 1 < nIter) prefetchKV(m0 + 64, cur ^ 1);

        const unsigned* Kst = smu + ATT_KS + cur * ATT_KS_W;
        const unsigned* Vst = smu + ATT_VS + cur * ATT_VS_W;

        // ---- QK^T ----
        float sacc[4][4];
#pragma unroll
        for (int i = 0; i < 4; i++)
#pragma unroll
            for (int j = 0; j < 4; j++) sacc[i][j] = 0.f;
#pragma unroll
        for (int ks = 0; ks < 8; ks++) {
            unsigned b0[4], b1[4];
#pragma unroll
            for (int nt = 0; nt < 4; nt++) {
                int mr = wn * 32 + nt * 8 + l4;
                b0[nt] = Kst[mr * 68 + ks * 8 + l3];
                b1[nt] = Kst[mr * 68 + ks * 8 + l3 + 4];
            }
#pragma unroll
            for (int nt = 0; nt < 4; nt++)
                mma8(sacc[nt], qf[ks][0], qf[ks][1], qf[ks][2], qf[ks][3], b0[nt], b1[nt]);
        }

        // ---- silu (tanh form) + mask, store S ----
        // silu(z)*invN with z = s*0.125:  s*c1*(0.5*tanh(s*0.0625)+0.5)
        bool easy = (m0 + 64 <= q0) && (q0 + 64 <= lim);
        if (easy) {
#pragma unroll
            for (int nt = 0; nt < 4; nt++) {
#pragma unroll
                for (int q = 0; q < 4; q++) {
                    float s = sacc[nt][q];
                    float tg = tanh_(s * 0.0625f);
                    sacc[nt][q] = (s * c1) * fmaf(0.5f, tg, 0.5f);
                }
                int sr = wm * 16 + l4;
                int sc = wn * 32 + nt * 8 + 2 * l3;
                *(float2*)&Ss[sr][sc] = make_float2(sacc[nt][0], sacc[nt][1]);
                *(float2*)&Ss[sr + 8][sc] = make_float2(sacc[nt][2], sacc[nt][3]);
            }
        } else {
            int n_lo = q0 + wm * 16 + l4;
            int n_hi = n_lo + 8;
            int idn_lo = min(n_lo, lim), idn_hi = min(n_hi, lim);
            bool nok_lo = n_lo < len, nok_hi = n_hi < len;
#pragma unroll
            for (int nt = 0; nt < 4; nt++) {
                int m_ = m0 + wn * 32 + nt * 8 + 2 * l3;
#pragma unroll
                for (int jj = 0; jj < 2; jj++) {
                    int m = m_ + jj;
                    int idm = min(m, lim);
                    bool mok = m < len;
                    float s0 = sacc[nt][jj];
                    float w0 = (s0 * c1) * fmaf(0.5f, tanh_(s0 * 0.0625f), 0.5f);
                    bool ok0 = mok && nok_lo && ((idn_lo > idm) || (n_lo == m));
                    sacc[nt][jj] = ok0 ? w0 : 0.f;
                    float s1 = sacc[nt][jj + 2];
                    float w1 = (s1 * c1) * fmaf(0.5f, tanh_(s1 * 0.0625f), 0.5f);
                    bool ok1 = mok && nok_hi && ((idn_hi > idm) || (n_hi == m));
                    sacc[nt][jj + 2] = ok1 ? w1 : 0.f;
                }
                int sr = wm * 16 + l4;
                int sc = wn * 32 + nt * 8 + 2 * l3;
                *(float2*)&Ss[sr][sc] = make_float2(sacc[nt][0], sacc[nt][1]);
                *(float2*)&Ss[sr + 8][sc] = make_float2(sacc[nt][2], sacc[nt][3]);
            }
        }
        __syncthreads();  // S visible block-wide

        // ---- PV ----
#pragma unroll
        for (int km = 0; km < 8; km++) {
            unsigned a0 = __float_as_uint(Ss[wm * 16 + l4][km * 8 + l3]);
            unsigned a1 = __float_as_uint(Ss[wm * 16 + l4 + 8][km * 8 + l3]);
            unsigned a2 = __float_as_uint(Ss[wm * 16 + l4][km * 8 + l3 + 4]);
            unsigned a3 = __float_as_uint(Ss[wm * 16 + l4 + 8][km * 8 + l3 + 4]);
#pragma unroll
            for (int nt = 0; nt < 4; nt++) {
                unsigned b0 = Vst[(km * 8 + l3) * 72 + wn * 32 + nt * 8 + l4];
                unsigned b1 = Vst[(km * 8 + l3 + 4) * 72 + wn * 32 + nt * 8 + l4];
                mma8(oacc[nt], a0, a1, a2, a3, b0, b1);
            }
        }
        cur ^= 1;
    }

#pragma unroll
    for (int nt = 0; nt < 4; nt++) {
        int col = h * 64 + wn * 32 + nt * 8 + 2 * l3;
        int n = q0 + wm * 16 + l4;
        if (n < len)
            *(float2*)&g_attn[(size_t)(off + n) * 256 + col] =
                make_float2(oacc[nt][0], oacc[nt][1]);
        if (n + 8 < len)
            *(float2*)&g_attn[(size_t)(off + n + 8) * 256 + col] =
                make_float2(oacc[nt][2], oacc[nt][3]);
    }
}

extern "C" void kernel_launch(void* const* d_in, const int* in_sizes, int n_in,
                              void* d_out, int out_size) {
    const float* x = (const float*)d_in[0];
    const int* xl = (const int*)d_in[1];
    const int* xo = (const int*)d_in[2];
    const int* msl = (const int*)d_in[3];
    const int* nt = (const int*)d_in[4];
    const float* Wu = (const float*)d_in[5];
    const float* bu = (const float*)d_in[6];
    const float* inw = (const float*)d_in[7];
    const float* inb = (const float*)d_in[8];
    const float* onw = (const float*)d_in[9];
    const float* onb = (const float*)d_in[10];
    const float* Wo = (const float*)d_in[11];
    float* out = (float*)d_out;

    int L = in_sizes[0] / 512;
    int B = in_sizes[1];

    static bool attr_set = false;
    if (!attr_set) {
        cudaFuncSetAttribute(k_attn_tc, cudaFuncAttributeMaxDynamicSharedMemorySize,
                             ATT_SMEM);
        cudaFuncSetAttribute(k_gemm1_tc, cudaFuncAttributeMaxDynamicSharedMemorySize,
                             GEMM_SMEM);
        cudaFuncSetAttribute(k_gemm2_tc, cudaFuncAttributeMaxDynamicSharedMemorySize,
                             GEMM_SMEM);
        attr_set = true;
    }

    k_ln_in<<<(L + 7) / 8, 256>>>(x, inw, inb, L);

    dim3 g1(1024 / 128, (L + 127) / 128);
    k_gemm1_tc<<<g1, 256, GEMM_SMEM>>>(Wu, bu, L);

    int TPB = (L + 63) / 64;
    dim3 ga(B * TPB, HH);
    k_attn_tc<<<ga, 256, ATT_SMEM>>>(xl, xo, nt, msl, TPB);

    k_ln_out<<<(L + 7) / 8, 256>>>(onw, onb, L);

    dim3 g2(512 / 128, (L + 127) / 128);
    k_gemm2_tc<<<g2, 256, GEMM_SMEM>>>(x, Wo, L, out);
}